// round 11
// baseline (speedup 1.0000x reference)
#include <cuda_runtime.h>
#include <cuda_bf16.h>
#include <math.h>
#include <stdint.h>

#define BB 32
#define TT_TOT 1500
#define SS 256

typedef __nv_bfloat16 bf16;

// ---------------- scratch buffers (device globals) --------------------------
__device__ __align__(16) bf16 g_actT0[BB * SS * 512];
__device__ __align__(16) bf16 g_actT1[BB * SS * 512];
__device__ __align__(16) bf16 g_cT[BB * SS * 1024];
__device__ __align__(16) bf16 g_kT[BB * SS * 96];
__device__ __align__(16) bf16 g_melsT[BB * TT_TOT * 96];
__device__ __align__(16) bf16 g_q0T[(size_t)BB * TT_TOT * 192];
__device__ __align__(16) bf16 g_q1T[(size_t)BB * TT_TOT * 128];
__device__ __align__(16) bf16 g_q2T[BB * TT_TOT * 96];
// per-layer repacked weights
__device__ __align__(16) bf16 g_w0[512 * 2560];
__device__ __align__(16) bf16 g_w1[512 * 2560];
__device__ __align__(16) bf16 g_w2[512 * 2560];
__device__ __align__(16) bf16 g_w3[1024 * 1536];
__device__ __align__(16) bf16 g_w4[128 * 1024];
__device__ __align__(16) bf16 g_wq0[256 * 288];
__device__ __align__(16) bf16 g_wq1[128 * 192];
__device__ __align__(16) bf16 g_wq2[128 * 128];
__device__ float g_k2v[BB * SS];
__device__ __align__(16) bf16 g_zero[8];  // zero page

// ---------------- helpers ----------------------------------------------------
__device__ __forceinline__ uint32_t smem_u32(const void* p) {
    uint32_t a;
    asm("{ .reg .u64 t; cvta.to.shared.u64 t, %1; cvt.u32.u64 %0, t; }"
        : "=r"(a) : "l"(p));
    return a;
}
__device__ __forceinline__ void cp16(void* smem, const void* gmem) {
    asm volatile("cp.async.cg.shared.global [%0], [%1], 16;"
                 :: "r"(smem_u32(smem)), "l"(gmem) : "memory");
}
#define CP_COMMIT() asm volatile("cp.async.commit_group;" ::: "memory")
#define CP_WAIT0() asm volatile("cp.async.wait_group 0;" ::: "memory")

__device__ __forceinline__ void mma16816(float* d, const uint32_t* a,
                                         const uint32_t* b) {
    asm volatile(
        "mma.sync.aligned.m16n8k16.row.col.f32.bf16.bf16.f32 "
        "{%0,%1,%2,%3}, {%4,%5,%6,%7}, {%8,%9}, {%0,%1,%2,%3};"
        : "+f"(d[0]), "+f"(d[1]), "+f"(d[2]), "+f"(d[3])
        : "r"(a[0]), "r"(a[1]), "r"(a[2]), "r"(a[3]), "r"(b[0]), "r"(b[1]));
}
__device__ __forceinline__ void ldsm4(uint32_t& r0, uint32_t& r1, uint32_t& r2,
                                      uint32_t& r3, uint32_t addr) {
    asm volatile("ldmatrix.sync.aligned.m8n8.x4.shared.b16 {%0,%1,%2,%3}, [%4];"
                 : "=r"(r0), "=r"(r1), "=r"(r2), "=r"(r3) : "r"(addr));
}

// ---------------- embedding: actT[b][s][c] (vectorized 8/thread) ------------
__global__ void embed_kernel(const int* __restrict__ ph,
                             const float* __restrict__ emb,
                             bf16* __restrict__ out) {
    int idx = blockIdx.x * blockDim.x + threadIdx.x;
    if (idx >= BB * SS * 64) return;
    int c8 = idx & 63;
    int s = (idx >> 6) & (SS - 1);
    int b = idx >> 14;
    const float* src = emb + (size_t)ph[b * SS + s] * 512 + c8 * 8;
    float4 f0 = *(const float4*)src;
    float4 f1 = *(const float4*)(src + 4);
    bf16 v[8];
    v[0] = __float2bfloat16(f0.x); v[1] = __float2bfloat16(f0.y);
    v[2] = __float2bfloat16(f0.z); v[3] = __float2bfloat16(f0.w);
    v[4] = __float2bfloat16(f1.x); v[5] = __float2bfloat16(f1.y);
    v[6] = __float2bfloat16(f1.z); v[7] = __float2bfloat16(f1.w);
    *(uint4*)(out + (size_t)idx * 8) = *(const uint4*)v;
}

// ------- fused weight repack (all layers, one launch) -----------------------
struct PrepArgs {
    const float* src[8];
    bf16* dst[8];
    int Cout[8], Cin[8], KT[8], CINP[8], total[8];
};
__global__ __launch_bounds__(256) void prep_all(PrepArgs pa) {
    int L = blockIdx.y;
    int idx8 = (blockIdx.x * 256 + threadIdx.x) * 8;
    if (idx8 >= pa.total[L]) return;
    const int CINP = pa.CINP[L], KTv = pa.KT[L], Cin = pa.Cin[L],
              Cout = pa.Cout[L];
    const int Ktot = CINP * KTv;
    int co = idx8 / Ktot, k = idx8 - co * Ktot;
    int t = k / CINP, ci = k - t * CINP;
    const float* w = pa.src[L];
    bf16 v[8];
#pragma unroll
    for (int j = 0; j < 8; j++) {
        float f = (co < Cout && ci + j < Cin)
                      ? w[((size_t)co * Cin + ci + j) * KTv + t]
                      : 0.f;
        v[j] = __float2bfloat16(f);
    }
    *(uint4*)(pa.dst[L] + idx8) = *(const uint4*)v;
}

// ------- mels transpose: melsT[b][t][ci] (bf16, ci padded to 96) ------------
__global__ __launch_bounds__(256) void melsT_kernel(const float* __restrict__ mels,
                                                    bf16* __restrict__ melsT) {
    __shared__ float tile[32][33];
    const int b = blockIdx.z;
    const int c0 = blockIdx.y * 32;
    const int t0 = blockIdx.x * 32;
    const int tx = threadIdx.x & 31, ty = threadIdx.x >> 5;
#pragma unroll
    for (int p = 0; p < 4; p++) {
        int c = ty + p * 8;
        tile[c][tx] = (c0 + c < 80 && t0 + tx < TT_TOT)
                          ? mels[((size_t)b * 80 + c0 + c) * TT_TOT + t0 + tx]
                          : 0.f;
    }
    __syncthreads();
#pragma unroll
    for (int p = 0; p < 4; p++) {
        int t = ty + p * 8;
        if (t0 + t < TT_TOT)
            melsT[((size_t)b * TT_TOT + t0 + t) * 96 + c0 + tx] =
                __float2bfloat16(tile[tx][t]);
    }
}

// ---------------- fused conv-as-GEMM (HMMA bf16 + ldmatrix) -----------------
// Block 128co x 64s, 8 warps (4co x 2s), warp tile 32x32. 2-stage ring.
// 3 CTAs/SM (regs capped at ~85 via launch_bounds).
template <int KT, int CINP, int CHUNK, bool RELU>
__global__ __launch_bounds__(256, 3) void gemm_conv(
    const bf16* __restrict__ Aw, const bf16* __restrict__ actT,
    const float* __restrict__ bias, bf16* __restrict__ outT,
    int Cout, int CS, int L) {
    constexpr int KTOT = KT * CINP;
    constexpr int NCH = KTOT / CHUNK;
    constexpr int PAD = KT / 2;
    constexpr int RP = CHUNK + 8;
    constexpr int UPR = CHUNK / 8;
    constexpr int KKN = CHUNK / 16;
    constexpr int STG = (128 + 64) * RP;  // elems per stage (A 128 rows, B 64)
    extern __shared__ __align__(16) bf16 dyn[];

    const int tid = threadIdx.x;
    const int wid = tid >> 5, lane = tid & 31;
    const int wm = wid >> 1, wn = wid & 1;  // 4 x 2 warp grid
    const int lr = lane >> 2, lc = (lane & 3) * 2;
    const int b = blockIdx.z, co0 = blockIdx.y * 128, s0 = blockIdx.x * 64;

    const bf16* gA = Aw + (size_t)co0 * KTOT;
    const bf16* actB = actT + (size_t)b * L * CINP;

    const int lmA_off = ((lane & 7) + ((lane >> 3) & 1) * 8) * RP +
                        (lane >> 4) * 8;
    const int lmB_off = ((lane & 7) + ((lane >> 4) & 1) * 8) * RP +
                        ((lane >> 3) & 1) * 8;
    const uint32_t aLm0 = smem_u32(dyn + (wm * 32) * RP + lmA_off);
    const uint32_t bLm0 = smem_u32(dyn + 128 * RP + (wn * 32) * RP + lmB_off);
    constexpr uint32_t STGB = STG * 2;  // stage stride bytes

    float acc[2][4][4];
#pragma unroll
    for (int i = 0; i < 2; i++)
#pragma unroll
        for (int j = 0; j < 4; j++)
#pragma unroll
            for (int v = 0; v < 4; v++) acc[i][j][v] = 0.f;

    auto load_chunk = [&](int stg, int ch) {
        const int k0 = ch * CHUNK;
        bf16* dA = dyn + stg * STG;
        bf16* dB = dA + 128 * RP;
#pragma unroll
        for (int n = 0; n < UPR / 2; n++) {
            int i = tid + n * 256;
            int row = i / UPR, u = i % UPR;
            cp16(dA + row * RP + u * 8, gA + (size_t)row * KTOT + k0 + u * 8);
        }
#pragma unroll
        for (int n = 0; n < (UPR + 3) / 4; n++) {
            int i = tid + n * 256;
            if (UPR < 4 && i >= 64 * UPR) break;
            int row = i / UPR, u = i % UPR;
            int k = k0 + u * 8;
            int t = k / CINP;
            int ci = k - t * CINP;
            int gs = s0 + row + t - PAD;
            const bf16* src = (gs >= 0 && gs < L)
                                  ? actB + (size_t)gs * CINP + ci
                                  : g_zero;
            cp16(dB + row * RP + u * 8, src);
        }
        CP_COMMIT();
    };

    load_chunk(0, 0);

    for (int ch = 0; ch < NCH; ch++) {
        CP_WAIT0();
        __syncthreads();
        if (ch + 1 < NCH) load_chunk((ch + 1) & 1, ch + 1);
        const uint32_t aB = aLm0 + (ch & 1) * STGB;
        const uint32_t bB = bLm0 + (ch & 1) * STGB;
#pragma unroll
        for (int kk = 0; kk < KKN; kk++) {
            uint32_t af[2][4];
#pragma unroll
            for (int im = 0; im < 2; im++)
                ldsm4(af[im][0], af[im][1], af[im][2], af[im][3],
                      aB + (im * 16 * RP + kk * 16) * 2);
            uint32_t bfr[4][2];
#pragma unroll
            for (int h = 0; h < 2; h++)
                ldsm4(bfr[2 * h][0], bfr[2 * h][1], bfr[2 * h + 1][0],
                      bfr[2 * h + 1][1], bB + (h * 16 * RP + kk * 16) * 2);
#pragma unroll
            for (int im = 0; im < 2; im++)
#pragma unroll
                for (int in = 0; in < 4; in++)
                    mma16816(acc[im][in], af[im], bfr[in]);
        }
        __syncthreads();
    }

    // transposed epilogue: acc -> ep[s][co] (64 x 72 bf16) -> stores
    bf16* ep = dyn;
#pragma unroll
    for (int c = 0; c < 2; c++) {
        if ((wm >> 1) == c) {
#pragma unroll
            for (int im = 0; im < 2; im++) {
                int co_loc = (wm & 1) * 32 + im * 16 + lr;
                int gco = co0 + c * 64 + co_loc;
                float b0v = (gco < Cout) ? bias[gco] : 0.f;
                float b1v = (gco + 8 < Cout) ? bias[gco + 8] : 0.f;
#pragma unroll
                for (int in = 0; in < 4; in++) {
                    int sl = wn * 32 + in * 8 + lc;
                    float* d = acc[im][in];
                    float v0 = d[0] + b0v, v1 = d[1] + b0v;
                    float v2 = d[2] + b1v, v3 = d[3] + b1v;
                    if (RELU) {
                        v0 = fmaxf(v0, 0.f); v1 = fmaxf(v1, 0.f);
                        v2 = fmaxf(v2, 0.f); v3 = fmaxf(v3, 0.f);
                    }
                    ep[sl * 72 + co_loc] = __float2bfloat16(v0);
                    ep[(sl + 1) * 72 + co_loc] = __float2bfloat16(v1);
                    ep[sl * 72 + co_loc + 8] = __float2bfloat16(v2);
                    ep[(sl + 1) * 72 + co_loc + 8] = __float2bfloat16(v3);
                }
            }
        }
        __syncthreads();
        int w = CS - (co0 + c * 64);
        if (w > 64) w = 64;
        if (w > 0) {
            int vpr = w >> 3;
            int tot = 64 * vpr;
            for (int idx = tid; idx < tot; idx += 256) {
                int s = idx / vpr, v = idx - s * vpr;
                if (s0 + s < L)
                    *(uint4*)(outT + ((size_t)b * L + s0 + s) * CS + co0 +
                              c * 64 + v * 8) = *(const uint4*)(ep + s * 72 + v * 8);
            }
        }
        __syncthreads();
    }
}

// ---------------- k squared-norm from kT [b][s][96] -------------------------
__global__ void k2_kernel(const bf16* __restrict__ kT, float* __restrict__ k2) {
    int idx = blockIdx.x * blockDim.x + threadIdx.x;
    if (idx >= BB * SS) return;
    const bf16* p = kT + (size_t)idx * 96;
    float sum = 0.f;
#pragma unroll
    for (int c = 0; c < 96; c++) {
        float v = __bfloat162float(p[c]);
        sum = fmaf(v, v, sum);
    }
    k2[idx] = sum;
}

// ---------------- HMMA attention: qk + log_softmax + prior + mask -----------
__global__ __launch_bounds__(256) void attn_mma(
    const bf16* __restrict__ q2T, const bf16* __restrict__ kT,
    const float* __restrict__ k2, const float* __restrict__ prior,
    const int* __restrict__ mask, float* __restrict__ out) {
    constexpr float TEMP = 0.0005f;
    constexpr int RP = 104;
    extern __shared__ __align__(16) bf16 dynA[];
    bf16* sQ = dynA;
    bf16* sK = dynA + 64 * RP;
    float* k2s = (float*)(dynA + (64 + 256) * RP);
    float* redM = k2s + 256;
    float* redS = redM + 256;
    float* lseS = redS + 256;

    const int tid = threadIdx.x;
    const int wid = tid >> 5, lane = tid & 31;
    const int wm = wid >> 2, wn = wid & 3;
    const int lr = lane >> 2, qq = lane & 3, lc = qq * 2;
    const int b = blockIdx.y, t0 = blockIdx.x * 64;

#pragma unroll
    for (int n = 0; n < 3; n++) {
        int i = tid + n * 256;
        int row = i / 12, u = i % 12;
        int gt = t0 + row;
        const bf16* src = (gt < TT_TOT)
                              ? q2T + ((size_t)b * TT_TOT + gt) * 96 + u * 8
                              : g_zero;
        cp16(sQ + row * RP + u * 8, src);
    }
#pragma unroll
    for (int n = 0; n < 12; n++) {
        int i = tid + n * 256;
        int row = i / 12, u = i % 12;
        cp16(sK + row * RP + u * 8, kT + ((size_t)b * SS + row) * 96 + u * 8);
    }
    k2s[tid] = k2[b * SS + tid];
    CP_COMMIT();
    CP_WAIT0();
    __syncthreads();

    const int lmA_off = ((lane & 7) + ((lane >> 3) & 1) * 8) * RP +
                        (lane >> 4) * 8;
    const int lmB_off = ((lane & 7) + ((lane >> 4) & 1) * 8) * RP +
                        ((lane >> 3) & 1) * 8;
    const uint32_t aB = smem_u32(sQ + (wm * 32) * RP + lmA_off);
    const uint32_t bB = smem_u32(sK + (wn * 64) * RP + lmB_off);

    float acc[2][8][4];
#pragma unroll
    for (int i = 0; i < 2; i++)
#pragma unroll
        for (int j = 0; j < 8; j++)
#pragma unroll
            for (int v = 0; v < 4; v++) acc[i][j][v] = 0.f;

#pragma unroll
    for (int kk = 0; kk < 6; kk++) {
        uint32_t af[2][4];
#pragma unroll
        for (int im = 0; im < 2; im++)
            ldsm4(af[im][0], af[im][1], af[im][2], af[im][3],
                  aB + (im * 16 * RP + kk * 16) * 2);
        uint32_t bfr[8][2];
#pragma unroll
        for (int h = 0; h < 4; h++)
            ldsm4(bfr[2 * h][0], bfr[2 * h][1], bfr[2 * h + 1][0],
                  bfr[2 * h + 1][1], bB + (h * 16 * RP + kk * 16) * 2);
#pragma unroll
        for (int im = 0; im < 2; im++)
#pragma unroll
            for (int in = 0; in < 8; in++)
                mma16816(acc[im][in], af[im], bfr[in]);
    }

#pragma unroll
    for (int im = 0; im < 2; im++)
#pragma unroll
        for (int in = 0; in < 8; in++) {
            int s = wn * 64 + in * 8 + lc;
            float2 kv = *(float2*)&k2s[s];
            acc[im][in][0] = TEMP * (2.f * acc[im][in][0] - kv.x);
            acc[im][in][1] = TEMP * (2.f * acc[im][in][1] - kv.y);
            acc[im][in][2] = TEMP * (2.f * acc[im][in][2] - kv.x);
            acc[im][in][3] = TEMP * (2.f * acc[im][in][3] - kv.y);
        }

#pragma unroll
    for (int im = 0; im < 2; im++)
#pragma unroll
        for (int h = 0; h < 2; h++) {
            float m = -INFINITY, se = 0.f;
#pragma unroll
            for (int in = 0; in < 8; in++) {
                float v0 = acc[im][in][2 * h], v1 = acc[im][in][2 * h + 1];
                float M = fmaxf(m, fmaxf(v0, v1));
                se = se * __expf(m - M) + __expf(v0 - M) + __expf(v1 - M);
                m = M;
            }
#pragma unroll
            for (int o = 1; o <= 2; o <<= 1) {
                float m2 = __shfl_xor_sync(~0u, m, o);
                float s2 = __shfl_xor_sync(~0u, se, o);
                float M = fmaxf(m, m2);
                se = se * __expf(m - M) + s2 * __expf(m2 - M);
                m = M;
            }
            if (qq == 0) {
                int row = wm * 32 + im * 16 + h * 8 + lr;
                redM[wn * 64 + row] = m;
                redS[wn * 64 + row] = se;
            }
        }
    __syncthreads();
    if (tid < 64) {
        float M = redM[tid], SE = redS[tid];
#pragma unroll
        for (int i = 1; i < 4; i++) {
            float mi = redM[i * 64 + tid], si = redS[i * 64 + tid];
            float Mn = fmaxf(M, mi);
            SE = SE * __expf(M - Mn) + si * __expf(mi - Mn);
            M = Mn;
        }
        lseS[tid] = M + __logf(SE);
    }
    __syncthreads();

#pragma unroll
    for (int im = 0; im < 2; im++)
#pragma unroll
        for (int h = 0; h < 2; h++) {
            int row = wm * 32 + im * 16 + h * 8 + lr;
            int t = t0 + row;
            if (t < TT_TOT) {
                float lse = lseS[row];
                size_t base = ((size_t)b * TT_TOT + t) * SS;
#pragma unroll
                for (int in = 0; in < 8; in++) {
                    int s = wn * 64 + in * 8 + lc;
                    size_t o = base + s;
                    float2 pr = *(const float2*)&prior[o];
                    int2 mk = *(const int2*)&mask[o];
                    float v0 = acc[im][in][2 * h] - lse + __logf(pr.x + 1e-8f);
                    float v1 = acc[im][in][2 * h + 1] - lse + __logf(pr.y + 1e-8f);
                    float2 res;
                    res.x = mk.x ? v0 : -INFINITY;
                    res.y = mk.y ? v1 : -INFINITY;
                    *(float2*)&out[o] = res;
                }
            }
        }
}

// ---------------- launch ----------------------------------------------------
extern "C" void kernel_launch(void* const* d_in, const int* in_sizes, int n_in,
                              void* d_out, int out_size) {
    const int* phonemes = (const int*)d_in[0];
    const float* mels = (const float*)d_in[1];
    const int* mask = (const int*)d_in[2];
    const float* prior = (const float*)d_in[3];
    const float* emb = (const float*)d_in[4];
    const float* kw[5] = {(const float*)d_in[5], (const float*)d_in[7],
                          (const float*)d_in[9], (const float*)d_in[11],
                          (const float*)d_in[13]};
    const float* kb[5] = {(const float*)d_in[6], (const float*)d_in[8],
                          (const float*)d_in[10], (const float*)d_in[12],
                          (const float*)d_in[14]};
    const float* qw[3] = {(const float*)d_in[15], (const float*)d_in[17],
                          (const float*)d_in[19]};
    const float* qb[3] = {(const float*)d_in[16], (const float*)d_in[18],
                          (const float*)d_in[20]};
    float* out = (float*)d_out;

    bf16 *pA0, *pA1, *pCT, *pKT, *pMT, *pQ0, *pQ1, *pQ2;
    bf16* pw[8];
    float* pk2;
    cudaGetSymbolAddress((void**)&pA0, g_actT0);
    cudaGetSymbolAddress((void**)&pA1, g_actT1);
    cudaGetSymbolAddress((void**)&pCT, g_cT);
    cudaGetSymbolAddress((void**)&pKT, g_kT);
    cudaGetSymbolAddress((void**)&pMT, g_melsT);
    cudaGetSymbolAddress((void**)&pQ0, g_q0T);
    cudaGetSymbolAddress((void**)&pQ1, g_q1T);
    cudaGetSymbolAddress((void**)&pQ2, g_q2T);
    cudaGetSymbolAddress((void**)&pw[0], g_w0);
    cudaGetSymbolAddress((void**)&pw[1], g_w1);
    cudaGetSymbolAddress((void**)&pw[2], g_w2);
    cudaGetSymbolAddress((void**)&pw[3], g_w3);
    cudaGetSymbolAddress((void**)&pw[4], g_w4);
    cudaGetSymbolAddress((void**)&pw[5], g_wq0);
    cudaGetSymbolAddress((void**)&pw[6], g_wq1);
    cudaGetSymbolAddress((void**)&pw[7], g_wq2);
    cudaGetSymbolAddress((void**)&pk2, g_k2v);

    // dynamic smem (2-stage, 192 rows x RP)
    const int SM64 = 2 * 192 * 72 * 2;   // 55296
    const int SM32 = 2 * 192 * 40 * 2;   // 30720
    const int SMATT = (64 + 256) * 104 * 2 + (256 * 3 + 64) * 4;  // 69888
    cudaFuncSetAttribute(gemm_conv<5, 512, 64, true>,
                         cudaFuncAttributeMaxDynamicSharedMemorySize, SM64);
    cudaFuncSetAttribute(gemm_conv<3, 512, 64, true>,
                         cudaFuncAttributeMaxDynamicSharedMemorySize, SM64);
    cudaFuncSetAttribute(gemm_conv<1, 1024, 64, false>,
                         cudaFuncAttributeMaxDynamicSharedMemorySize, SM64);
    cudaFuncSetAttribute(gemm_conv<3, 96, 32, true>,
                         cudaFuncAttributeMaxDynamicSharedMemorySize, SM32);
    cudaFuncSetAttribute(gemm_conv<1, 192, 64, true>,
                         cudaFuncAttributeMaxDynamicSharedMemorySize, SM64);
    cudaFuncSetAttribute(gemm_conv<1, 128, 64, false>,
                         cudaFuncAttributeMaxDynamicSharedMemorySize, SM64);
    cudaFuncSetAttribute(attn_mma,
                         cudaFuncAttributeMaxDynamicSharedMemorySize, SMATT);

    // embedding + mels transpose
    embed_kernel<<<(BB * SS * 64 + 255) / 256, 256>>>(phonemes, emb, pA0);
    melsT_kernel<<<dim3(47, 3, BB), 256>>>(mels, pMT);

    // all weight repacks in one launch
    PrepArgs pa;
    const int CoutA[8] = {512, 512, 512, 1024, 80, 160, 80, 80};
    const int CinA[8] = {512, 512, 512, 512, 1024, 80, 160, 80};
    const int KTA[8] = {5, 5, 5, 3, 1, 3, 1, 1};
    const int CINPA[8] = {512, 512, 512, 512, 1024, 96, 192, 128};
    const int RPAD[8] = {512, 512, 512, 1024, 128, 256, 128, 128};
    const float* srcs[8] = {kw[0], kw[1], kw[2], kw[3], kw[4],
                            qw[0], qw[1], qw[2]};
    for (int i = 0; i < 8; i++) {
        pa.src[i] = srcs[i];
        pa.dst[i] = pw[i];
        pa.Cout[i] = CoutA[i];
        pa.Cin[i] = CinA[i];
        pa.KT[i] = KTA[i];
        pa.CINP[i] = CINPA[i];
        pa.total[i] = RPAD[i] * KTA[i] * CINPA[i];
    }
    prep_all<<<dim3(768, 8), 256>>>(pa);

    // ---- key encoder ----
    gemm_conv<5, 512, 64, true><<<dim3(4, 4, BB), 256, SM64>>>(
        pw[0], pA0, kb[0], pA1, 512, 512, SS);
    gemm_conv<5, 512, 64, true><<<dim3(4, 4, BB), 256, SM64>>>(
        pw[1], pA1, kb[1], pA0, 512, 512, SS);
    gemm_conv<5, 512, 64, true><<<dim3(4, 4, BB), 256, SM64>>>(
        pw[2], pA0, kb[2], pA1, 512, 512, SS);
    gemm_conv<3, 512, 64, true><<<dim3(4, 8, BB), 256, SM64>>>(
        pw[3], pA1, kb[3], pCT, 1024, 1024, SS);
    gemm_conv<1, 1024, 64, false><<<dim3(4, 1, BB), 256, SM64>>>(
        pw[4], pCT, kb[4], pKT, 80, 96, SS);

    k2_kernel<<<(BB * SS + 255) / 256, 256>>>(pKT, pk2);

    // ---- query encoder ----
    gemm_conv<3, 96, 32, true><<<dim3(24, 2, BB), 256, SM32>>>(
        pw[5], pMT, qb[0], pQ0, 160, 192, TT_TOT);
    gemm_conv<1, 192, 64, true><<<dim3(24, 1, BB), 256, SM64>>>(
        pw[6], pQ0, qb[1], pQ1, 80, 128, TT_TOT);
    gemm_conv<1, 128, 64, false><<<dim3(24, 1, BB), 256, SM64>>>(
        pw[7], pQ1, qb[2], pQ2, 80, 96, TT_TOT);

    // HMMA attention + log_softmax + prior + mask
    attn_mma<<<dim3((TT_TOT + 63) / 64, BB), 256, SMATT>>>(pQ2, pKT, pk2,
                                                           prior, mask, out);
}

// round 15
// speedup vs baseline: 1.1697x; 1.1697x over previous
#include <cuda_runtime.h>
#include <cuda_bf16.h>
#include <math.h>
#include <stdint.h>

#define BB 32
#define TT_TOT 1500
#define SS 256

typedef __nv_bfloat16 bf16;

// ---------------- scratch buffers (device globals) --------------------------
__device__ __align__(16) bf16 g_actT0[BB * SS * 512];
__device__ __align__(16) bf16 g_actT1[BB * SS * 512];
__device__ __align__(16) bf16 g_cT[BB * SS * 1024];
__device__ __align__(16) bf16 g_kT[BB * SS * 96];
__device__ __align__(16) bf16 g_melsT[BB * TT_TOT * 96];
__device__ __align__(16) bf16 g_q0T[(size_t)BB * TT_TOT * 192];
__device__ __align__(16) bf16 g_q1T[(size_t)BB * TT_TOT * 128];
__device__ __align__(16) bf16 g_q2T[BB * TT_TOT * 96];
// per-layer repacked weights
__device__ __align__(16) bf16 g_w0[512 * 2560];
__device__ __align__(16) bf16 g_w1[512 * 2560];
__device__ __align__(16) bf16 g_w2[512 * 2560];
__device__ __align__(16) bf16 g_w3[1024 * 1536];
__device__ __align__(16) bf16 g_w4[128 * 1024];
__device__ __align__(16) bf16 g_wq0[256 * 288];
__device__ __align__(16) bf16 g_wq1[128 * 192];
__device__ __align__(16) bf16 g_wq2[128 * 128];
__device__ float g_k2v[BB * SS];
__device__ __align__(16) bf16 g_zero[8];  // zero page

// ---------------- helpers ----------------------------------------------------
__device__ __forceinline__ uint32_t smem_u32(const void* p) {
    uint32_t a;
    asm("{ .reg .u64 t; cvta.to.shared.u64 t, %1; cvt.u32.u64 %0, t; }"
        : "=r"(a) : "l"(p));
    return a;
}
__device__ __forceinline__ void cp16(void* smem, const void* gmem) {
    asm volatile("cp.async.cg.shared.global [%0], [%1], 16;"
                 :: "r"(smem_u32(smem)), "l"(gmem) : "memory");
}
#define CP_COMMIT() asm volatile("cp.async.commit_group;" ::: "memory")
#define CP_WAIT0() asm volatile("cp.async.wait_group 0;" ::: "memory")
#define CP_WAIT1() asm volatile("cp.async.wait_group 1;" ::: "memory")

__device__ __forceinline__ void mma16816(float* d, const uint32_t* a,
                                         const uint32_t* b) {
    asm volatile(
        "mma.sync.aligned.m16n8k16.row.col.f32.bf16.bf16.f32 "
        "{%0,%1,%2,%3}, {%4,%5,%6,%7}, {%8,%9}, {%0,%1,%2,%3};"
        : "+f"(d[0]), "+f"(d[1]), "+f"(d[2]), "+f"(d[3])
        : "r"(a[0]), "r"(a[1]), "r"(a[2]), "r"(a[3]), "r"(b[0]), "r"(b[1]));
}
__device__ __forceinline__ void ldsm4(uint32_t& r0, uint32_t& r1, uint32_t& r2,
                                      uint32_t& r3, uint32_t addr) {
    asm volatile("ldmatrix.sync.aligned.m8n8.x4.shared.b16 {%0,%1,%2,%3}, [%4];"
                 : "=r"(r0), "=r"(r1), "=r"(r2), "=r"(r3) : "r"(addr));
}

// ---------------- embedding: actT[b][s][c] (vectorized 8/thread) ------------
__global__ void embed_kernel(const int* __restrict__ ph,
                             const float* __restrict__ emb,
                             bf16* __restrict__ out) {
    int idx = blockIdx.x * blockDim.x + threadIdx.x;
    if (idx >= BB * SS * 64) return;
    int c8 = idx & 63;
    int s = (idx >> 6) & (SS - 1);
    int b = idx >> 14;
    const float* src = emb + (size_t)ph[b * SS + s] * 512 + c8 * 8;
    float4 f0 = *(const float4*)src;
    float4 f1 = *(const float4*)(src + 4);
    bf16 v[8];
    v[0] = __float2bfloat16(f0.x); v[1] = __float2bfloat16(f0.y);
    v[2] = __float2bfloat16(f0.z); v[3] = __float2bfloat16(f0.w);
    v[4] = __float2bfloat16(f1.x); v[5] = __float2bfloat16(f1.y);
    v[6] = __float2bfloat16(f1.z); v[7] = __float2bfloat16(f1.w);
    *(uint4*)(out + (size_t)idx * 8) = *(const uint4*)v;
}

// ------- fused weight repack (all layers, one launch) -----------------------
struct PrepArgs {
    const float* src[8];
    bf16* dst[8];
    int Cout[8], Cin[8], KT[8], CINP[8], total[8];
};
__global__ __launch_bounds__(256) void prep_all(PrepArgs pa) {
    int L = blockIdx.y;
    int idx8 = (blockIdx.x * 256 + threadIdx.x) * 8;
    if (idx8 >= pa.total[L]) return;
    const int CINP = pa.CINP[L], KTv = pa.KT[L], Cin = pa.Cin[L],
              Cout = pa.Cout[L];
    const int Ktot = CINP * KTv;
    int co = idx8 / Ktot, k = idx8 - co * Ktot;
    int t = k / CINP, ci = k - t * CINP;
    const float* w = pa.src[L];
    bf16 v[8];
#pragma unroll
    for (int j = 0; j < 8; j++) {
        float f = (co < Cout && ci + j < Cin)
                      ? w[((size_t)co * Cin + ci + j) * KTv + t]
                      : 0.f;
        v[j] = __float2bfloat16(f);
    }
    *(uint4*)(pa.dst[L] + idx8) = *(const uint4*)v;
}

// ------- mels transpose: melsT[b][t][ci] (bf16, ci padded to 96) ------------
__global__ __launch_bounds__(256) void melsT_kernel(const float* __restrict__ mels,
                                                    bf16* __restrict__ melsT) {
    __shared__ float tile[32][33];
    const int b = blockIdx.z;
    const int c0 = blockIdx.y * 32;
    const int t0 = blockIdx.x * 32;
    const int tx = threadIdx.x & 31, ty = threadIdx.x >> 5;
#pragma unroll
    for (int p = 0; p < 4; p++) {
        int c = ty + p * 8;
        tile[c][tx] = (c0 + c < 80 && t0 + tx < TT_TOT)
                          ? mels[((size_t)b * 80 + c0 + c) * TT_TOT + t0 + tx]
                          : 0.f;
    }
    __syncthreads();
#pragma unroll
    for (int p = 0; p < 4; p++) {
        int t = ty + p * 8;
        if (t0 + t < TT_TOT)
            melsT[((size_t)b * TT_TOT + t0 + t) * 96 + c0 + tx] =
                __float2bfloat16(tile[tx][t]);
    }
}

// ---------------- fused conv-as-GEMM (HMMA bf16 + ldmatrix, 3-stage) --------
// Block 128co x 128s, 8 warps 2x4, warp tile 64x32, K chunk CHUNK, 3 stages.
template <int KT, int CINP, int CHUNK, bool RELU>
__global__ __launch_bounds__(256, 2) void gemm_conv(
    const bf16* __restrict__ Aw, const bf16* __restrict__ actT,
    const float* __restrict__ bias, bf16* __restrict__ outT,
    int Cout, int CS, int L) {
    constexpr int KTOT = KT * CINP;
    constexpr int NCH = KTOT / CHUNK;
    constexpr int PAD = KT / 2;
    constexpr int RP = CHUNK + 8;
    constexpr int UPR = CHUNK / 8;
    constexpr int KKN = CHUNK / 16;
    constexpr int STG = 2 * 128 * RP;   // elems per stage (A then B)
    extern __shared__ __align__(16) bf16 dyn[];

    const int tid = threadIdx.x;
    const int wid = tid >> 5, lane = tid & 31;
    const int wm = wid >> 2, wn = wid & 3;
    const int lr = lane >> 2, lc = (lane & 3) * 2;
    const int b = blockIdx.z, co0 = blockIdx.y * 128, s0 = blockIdx.x * 128;

    const bf16* gA = Aw + (size_t)co0 * KTOT;
    const bf16* actB = actT + (size_t)b * L * CINP;

    const int lmA_off = ((lane & 7) + ((lane >> 3) & 1) * 8) * RP +
                        (lane >> 4) * 8;
    const int lmB_off = ((lane & 7) + ((lane >> 4) & 1) * 8) * RP +
                        ((lane >> 3) & 1) * 8;
    const uint32_t aLm0 = smem_u32(dyn + (wm * 64) * RP + lmA_off);
    const uint32_t bLm0 = smem_u32(dyn + 128 * RP + (wn * 32) * RP + lmB_off);
    constexpr uint32_t STGB = STG * 2;  // stage stride bytes

    float acc[4][4][4];
#pragma unroll
    for (int i = 0; i < 4; i++)
#pragma unroll
        for (int j = 0; j < 4; j++)
#pragma unroll
            for (int v = 0; v < 4; v++) acc[i][j][v] = 0.f;

    auto load_chunk = [&](int stg, int ch) {
        const int k0 = ch * CHUNK;
        bf16* dA = dyn + stg * STG;
        bf16* dB = dA + 128 * RP;
#pragma unroll
        for (int n = 0; n < UPR / 2; n++) {
            int i = tid + n * 256;
            int row = i / UPR, u = i % UPR;
            cp16(dA + row * RP + u * 8, gA + (size_t)row * KTOT + k0 + u * 8);
        }
#pragma unroll
        for (int n = 0; n < UPR / 2; n++) {
            int i = tid + n * 256;
            int row = i / UPR, u = i % UPR;
            int k = k0 + u * 8;
            int t = k / CINP;
            int ci = k - t * CINP;
            int gs = s0 + row + t - PAD;
            const bf16* src = (gs >= 0 && gs < L)
                                  ? actB + (size_t)gs * CINP + ci
                                  : g_zero;
            cp16(dB + row * RP + u * 8, src);
        }
        CP_COMMIT();
    };

    load_chunk(0, 0);
    load_chunk(1, 1);

    int st = 0, st2 = 2;
    for (int ch = 0; ch < NCH; ch++) {
        if (ch + 1 < NCH) { CP_WAIT1(); } else { CP_WAIT0(); }
        __syncthreads();
        if (ch + 2 < NCH) load_chunk(st2, ch + 2);
        const uint32_t aB = aLm0 + st * STGB;
        const uint32_t bB = bLm0 + st * STGB;
#pragma unroll
        for (int kk = 0; kk < KKN; kk++) {
            uint32_t af[4][4];
#pragma unroll
            for (int im = 0; im < 4; im++)
                ldsm4(af[im][0], af[im][1], af[im][2], af[im][3],
                      aB + (im * 16 * RP + kk * 16) * 2);
            uint32_t bfr[4][2];
#pragma unroll
            for (int h = 0; h < 2; h++)
                ldsm4(bfr[2 * h][0], bfr[2 * h][1], bfr[2 * h + 1][0],
                      bfr[2 * h + 1][1], bB + (h * 16 * RP + kk * 16) * 2);
#pragma unroll
            for (int im = 0; im < 4; im++)
#pragma unroll
                for (int in = 0; in < 4; in++)
                    mma16816(acc[im][in], af[im], bfr[in]);
        }
        st = (st == 2) ? 0 : st + 1;
        st2 = (st2 == 2) ? 0 : st2 + 1;
    }
    __syncthreads();  // all reads done before ep overwrite

    // transposed epilogue: acc -> ep[s][co] (bf16, stride 72) -> stores
    bf16* ep = dyn;  // 128 x 72 bf16
#pragma unroll
    for (int c = 0; c < 2; c++) {
        if (wm == c) {
#pragma unroll
            for (int im = 0; im < 4; im++) {
                int co_loc = im * 16 + lr;
                int gco = co0 + c * 64 + co_loc;
                float b0v = (gco < Cout) ? bias[gco] : 0.f;
                float b1v = (gco + 8 < Cout) ? bias[gco + 8] : 0.f;
#pragma unroll
                for (int in = 0; in < 4; in++) {
                    int sl = wn * 32 + in * 8 + lc;
                    float* d = acc[im][in];
                    float v0 = d[0] + b0v, v1 = d[1] + b0v;
                    float v2 = d[2] + b1v, v3 = d[3] + b1v;
                    if (RELU) {
                        v0 = fmaxf(v0, 0.f); v1 = fmaxf(v1, 0.f);
                        v2 = fmaxf(v2, 0.f); v3 = fmaxf(v3, 0.f);
                    }
                    ep[sl * 72 + co_loc] = __float2bfloat16(v0);
                    ep[(sl + 1) * 72 + co_loc] = __float2bfloat16(v1);
                    ep[sl * 72 + co_loc + 8] = __float2bfloat16(v2);
                    ep[(sl + 1) * 72 + co_loc + 8] = __float2bfloat16(v3);
                }
            }
        }
        __syncthreads();
        int w = CS - (co0 + c * 64);
        if (w > 64) w = 64;
        if (w > 0) {
            int vpr = w >> 3;
            int tot = 128 * vpr;
            for (int idx = tid; idx < tot; idx += 256) {
                int s = idx / vpr, v = idx - s * vpr;
                if (s0 + s < L)
                    *(uint4*)(outT + ((size_t)b * L + s0 + s) * CS + co0 +
                              c * 64 + v * 8) = *(const uint4*)(ep + s * 72 + v * 8);
            }
        }
        __syncthreads();
    }
}

// ---------------- k squared-norm from kT [b][s][96] -------------------------
__global__ void k2_kernel(const bf16* __restrict__ kT, float* __restrict__ k2) {
    int idx = blockIdx.x * blockDim.x + threadIdx.x;
    if (idx >= BB * SS) return;
    const bf16* p = kT + (size_t)idx * 96;
    float sum = 0.f;
#pragma unroll
    for (int c = 0; c < 96; c++) {
        float v = __bfloat162float(p[c]);
        sum = fmaf(v, v, sum);
    }
    k2[idx] = sum;
}

// ---------------- HMMA attention: qk + log_softmax + prior + mask -----------
__global__ __launch_bounds__(256) void attn_mma(
    const bf16* __restrict__ q2T, const bf16* __restrict__ kT,
    const float* __restrict__ k2, const float* __restrict__ prior,
    const int* __restrict__ mask, float* __restrict__ out) {
    constexpr float TEMP = 0.0005f;
    constexpr int RP = 104;
    extern __shared__ __align__(16) bf16 dynA[];
    bf16* sQ = dynA;
    bf16* sK = dynA + 64 * RP;
    float* k2s = (float*)(dynA + (64 + 256) * RP);
    float* redM = k2s + 256;
    float* redS = redM + 256;
    float* lseS = redS + 256;

    const int tid = threadIdx.x;
    const int wid = tid >> 5, lane = tid & 31;
    const int wm = wid >> 2, wn = wid & 3;
    const int lr = lane >> 2, qq = lane & 3, lc = qq * 2;
    const int b = blockIdx.y, t0 = blockIdx.x * 64;

#pragma unroll
    for (int n = 0; n < 3; n++) {
        int i = tid + n * 256;
        int row = i / 12, u = i % 12;
        int gt = t0 + row;
        const bf16* src = (gt < TT_TOT)
                              ? q2T + ((size_t)b * TT_TOT + gt) * 96 + u * 8
                              : g_zero;
        cp16(sQ + row * RP + u * 8, src);
    }
#pragma unroll
    for (int n = 0; n < 12; n++) {
        int i = tid + n * 256;
        int row = i / 12, u = i % 12;
        cp16(sK + row * RP + u * 8, kT + ((size_t)b * SS + row) * 96 + u * 8);
    }
    k2s[tid] = k2[b * SS + tid];
    CP_COMMIT();
    CP_WAIT0();
    __syncthreads();

    const int lmA_off = ((lane & 7) + ((lane >> 3) & 1) * 8) * RP +
                        (lane >> 4) * 8;
    const int lmB_off = ((lane & 7) + ((lane >> 4) & 1) * 8) * RP +
                        ((lane >> 3) & 1) * 8;
    const uint32_t aB = smem_u32(sQ + (wm * 32) * RP + lmA_off);
    const uint32_t bB = smem_u32(sK + (wn * 64) * RP + lmB_off);

    float acc[2][8][4];
#pragma unroll
    for (int i = 0; i < 2; i++)
#pragma unroll
        for (int j = 0; j < 8; j++)
#pragma unroll
            for (int v = 0; v < 4; v++) acc[i][j][v] = 0.f;

#pragma unroll
    for (int kk = 0; kk < 6; kk++) {
        uint32_t af[2][4];
#pragma unroll
        for (int im = 0; im < 2; im++)
            ldsm4(af[im][0], af[im][1], af[im][2], af[im][3],
                  aB + (im * 16 * RP + kk * 16) * 2);
        uint32_t bfr[8][2];
#pragma unroll
        for (int h = 0; h < 4; h++)
            ldsm4(bfr[2 * h][0], bfr[2 * h][1], bfr[2 * h + 1][0],
                  bfr[2 * h + 1][1], bB + (h * 16 * RP + kk * 16) * 2);
#pragma unroll
        for (int im = 0; im < 2; im++)
#pragma unroll
            for (int in = 0; in < 8; in++)
                mma16816(acc[im][in], af[im], bfr[in]);
    }

#pragma unroll
    for (int im = 0; im < 2; im++)
#pragma unroll
        for (int in = 0; in < 8; in++) {
            int s = wn * 64 + in * 8 + lc;
            float2 kv = *(float2*)&k2s[s];
            acc[im][in][0] = TEMP * (2.f * acc[im][in][0] - kv.x);
            acc[im][in][1] = TEMP * (2.f * acc[im][in][1] - kv.y);
            acc[im][in][2] = TEMP * (2.f * acc[im][in][2] - kv.x);
            acc[im][in][3] = TEMP * (2.f * acc[im][in][3] - kv.y);
        }

#pragma unroll
    for (int im = 0; im < 2; im++)
#pragma unroll
        for (int h = 0; h < 2; h++) {
            float m = -INFINITY, se = 0.f;
#pragma unroll
            for (int in = 0; in < 8; in++) {
                float v0 = acc[im][in][2 * h], v1 = acc[im][in][2 * h + 1];
                float M = fmaxf(m, fmaxf(v0, v1));
                se = se * __expf(m - M) + __expf(v0 - M) + __expf(v1 - M);
                m = M;
            }
#pragma unroll
            for (int o = 1; o <= 2; o <<= 1) {
                float m2 = __shfl_xor_sync(~0u, m, o);
                float s2 = __shfl_xor_sync(~0u, se, o);
                float M = fmaxf(m, m2);
                se = se * __expf(m - M) + s2 * __expf(m2 - M);
                m = M;
            }
            if (qq == 0) {
                int row = wm * 32 + im * 16 + h * 8 + lr;
                redM[wn * 64 + row] = m;
                redS[wn * 64 + row] = se;
            }
        }
    __syncthreads();
    if (tid < 64) {
        float M = redM[tid], SE = redS[tid];
#pragma unroll
        for (int i = 1; i < 4; i++) {
            float mi = redM[i * 64 + tid], si = redS[i * 64 + tid];
            float Mn = fmaxf(M, mi);
            SE = SE * __expf(M - Mn) + si * __expf(mi - Mn);
            M = Mn;
        }
        lseS[tid] = M + __logf(SE);
    }
    __syncthreads();

#pragma unroll
    for (int im = 0; im < 2; im++)
#pragma unroll
        for (int h = 0; h < 2; h++) {
            int row = wm * 32 + im * 16 + h * 8 + lr;
            int t = t0 + row;
            if (t < TT_TOT) {
                float lse = lseS[row];
                size_t base = ((size_t)b * TT_TOT + t) * SS;
#pragma unroll
                for (int in = 0; in < 8; in++) {
                    int s = wn * 64 + in * 8 + lc;
                    size_t o = base + s;
                    float2 pr = *(const float2*)&prior[o];
                    int2 mk = *(const int2*)&mask[o];
                    float v0 = acc[im][in][2 * h] - lse + __logf(pr.x + 1e-8f);
                    float v1 = acc[im][in][2 * h + 1] - lse + __logf(pr.y + 1e-8f);
                    float2 res;
                    res.x = mk.x ? v0 : -INFINITY;
                    res.y = mk.y ? v1 : -INFINITY;
                    *(float2*)&out[o] = res;
                }
            }
        }
}

// ---------------- launch ----------------------------------------------------
extern "C" void kernel_launch(void* const* d_in, const int* in_sizes, int n_in,
                              void* d_out, int out_size) {
    const int* phonemes = (const int*)d_in[0];
    const float* mels = (const float*)d_in[1];
    const int* mask = (const int*)d_in[2];
    const float* prior = (const float*)d_in[3];
    const float* emb = (const float*)d_in[4];
    const float* kw[5] = {(const float*)d_in[5], (const float*)d_in[7],
                          (const float*)d_in[9], (const float*)d_in[11],
                          (const float*)d_in[13]};
    const float* kb[5] = {(const float*)d_in[6], (const float*)d_in[8],
                          (const float*)d_in[10], (const float*)d_in[12],
                          (const float*)d_in[14]};
    const float* qw[3] = {(const float*)d_in[15], (const float*)d_in[17],
                          (const float*)d_in[19]};
    const float* qb[3] = {(const float*)d_in[16], (const float*)d_in[18],
                          (const float*)d_in[20]};
    float* out = (float*)d_out;

    bf16 *pA0, *pA1, *pCT, *pKT, *pMT, *pQ0, *pQ1, *pQ2;
    bf16* pw[8];
    float* pk2;
    cudaGetSymbolAddress((void**)&pA0, g_actT0);
    cudaGetSymbolAddress((void**)&pA1, g_actT1);
    cudaGetSymbolAddress((void**)&pCT, g_cT);
    cudaGetSymbolAddress((void**)&pKT, g_kT);
    cudaGetSymbolAddress((void**)&pMT, g_melsT);
    cudaGetSymbolAddress((void**)&pQ0, g_q0T);
    cudaGetSymbolAddress((void**)&pQ1, g_q1T);
    cudaGetSymbolAddress((void**)&pQ2, g_q2T);
    cudaGetSymbolAddress((void**)&pw[0], g_w0);
    cudaGetSymbolAddress((void**)&pw[1], g_w1);
    cudaGetSymbolAddress((void**)&pw[2], g_w2);
    cudaGetSymbolAddress((void**)&pw[3], g_w3);
    cudaGetSymbolAddress((void**)&pw[4], g_w4);
    cudaGetSymbolAddress((void**)&pw[5], g_wq0);
    cudaGetSymbolAddress((void**)&pw[6], g_wq1);
    cudaGetSymbolAddress((void**)&pw[7], g_wq2);
    cudaGetSymbolAddress((void**)&pk2, g_k2v);

    // dynamic smem opt-in (3-stage ring)
    const int SM64 = 3 * 2 * 128 * 72 * 2;   // 110592
    const int SM32 = 3 * 2 * 128 * 40 * 2;   // 61440
    const int SMATT = (64 + 256) * 104 * 2 + (256 * 3 + 64) * 4;  // 69888
    cudaFuncSetAttribute(gemm_conv<5, 512, 64, true>,
                         cudaFuncAttributeMaxDynamicSharedMemorySize, SM64);
    cudaFuncSetAttribute(gemm_conv<3, 512, 64, true>,
                         cudaFuncAttributeMaxDynamicSharedMemorySize, SM64);
    cudaFuncSetAttribute(gemm_conv<1, 1024, 64, false>,
                         cudaFuncAttributeMaxDynamicSharedMemorySize, SM64);
    cudaFuncSetAttribute(gemm_conv<3, 96, 32, true>,
                         cudaFuncAttributeMaxDynamicSharedMemorySize, SM32);
    cudaFuncSetAttribute(gemm_conv<1, 192, 64, true>,
                         cudaFuncAttributeMaxDynamicSharedMemorySize, SM64);
    cudaFuncSetAttribute(gemm_conv<1, 128, 64, false>,
                         cudaFuncAttributeMaxDynamicSharedMemorySize, SM64);
    cudaFuncSetAttribute(attn_mma,
                         cudaFuncAttributeMaxDynamicSharedMemorySize, SMATT);

    // fork-join side stream (created fresh per invocation; kernel_launch runs
    // only for correctness + capture, so no unbounded resource growth)
    cudaStream_t sQ;
    cudaStreamCreateWithFlags(&sQ, cudaStreamNonBlocking);
    cudaEvent_t evFork, evPrep, evQ;
    cudaEventCreateWithFlags(&evFork, cudaEventDisableTiming);
    cudaEventCreateWithFlags(&evPrep, cudaEventDisableTiming);
    cudaEventCreateWithFlags(&evQ, cudaEventDisableTiming);

    // fork: side stream joins the (possibly capturing) legacy stream
    cudaEventRecord(evFork, 0);
    cudaStreamWaitEvent(sQ, evFork, 0);

    // main: embedding; side: mels transpose
    embed_kernel<<<(BB * SS * 64 + 255) / 256, 256>>>(phonemes, emb, pA0);
    melsT_kernel<<<dim3(47, 3, BB), 256, 0, sQ>>>(mels, pMT);

    // all weight repacks in one launch (main)
    PrepArgs pa;
    const int CoutA[8] = {512, 512, 512, 1024, 80, 160, 80, 80};
    const int CinA[8] = {512, 512, 512, 512, 1024, 80, 160, 80};
    const int KTA[8] = {5, 5, 5, 3, 1, 3, 1, 1};
    const int CINPA[8] = {512, 512, 512, 512, 1024, 96, 192, 128};
    const int RPAD[8] = {512, 512, 512, 1024, 128, 256, 128, 128};
    const float* srcs[8] = {kw[0], kw[1], kw[2], kw[3], kw[4],
                            qw[0], qw[1], qw[2]};
    for (int i = 0; i < 8; i++) {
        pa.src[i] = srcs[i];
        pa.dst[i] = pw[i];
        pa.Cout[i] = CoutA[i];
        pa.Cin[i] = CinA[i];
        pa.KT[i] = KTA[i];
        pa.CINP[i] = CINPA[i];
        pa.total[i] = RPAD[i] * KTA[i] * CINPA[i];
    }
    prep_all<<<dim3(768, 8), 256>>>(pa);
    cudaEventRecord(evPrep, 0);

    // ---- query encoder on side stream (fills idle SM slots of key chain) ---
    cudaStreamWaitEvent(sQ, evPrep, 0);
    gemm_conv<3, 96, 32, true><<<dim3(12, 2, BB), 256, SM32, sQ>>>(
        pw[5], pMT, qb[0], pQ0, 160, 192, TT_TOT);
    gemm_conv<1, 192, 64, true><<<dim3(12, 1, BB), 256, SM64, sQ>>>(
        pw[6], pQ0, qb[1], pQ1, 80, 128, TT_TOT);
    gemm_conv<1, 128, 64, false><<<dim3(12, 1, BB), 256, SM64, sQ>>>(
        pw[7], pQ1, qb[2], pQ2, 80, 96, TT_TOT);
    cudaEventRecord(evQ, sQ);

    // ---- key encoder on main stream ----
    gemm_conv<5, 512, 64, true><<<dim3(2, 4, BB), 256, SM64>>>(
        pw[0], pA0, kb[0], pA1, 512, 512, SS);
    gemm_conv<5, 512, 64, true><<<dim3(2, 4, BB), 256, SM64>>>(
        pw[1], pA1, kb[1], pA0, 512, 512, SS);
    gemm_conv<5, 512, 64, true><<<dim3(2, 4, BB), 256, SM64>>>(
        pw[2], pA0, kb[2], pA1, 512, 512, SS);
    gemm_conv<3, 512, 64, true><<<dim3(2, 8, BB), 256, SM64>>>(
        pw[3], pA1, kb[3], pCT, 1024, 1024, SS);
    gemm_conv<1, 1024, 64, false><<<dim3(2, 1, BB), 256, SM64>>>(
        pw[4], pCT, kb[4], pKT, 80, 96, SS);

    k2_kernel<<<(BB * SS + 255) / 256, 256>>>(pKT, pk2);

    // join: attention needs the query path
    cudaStreamWaitEvent(0, evQ, 0);

    // HMMA attention + log_softmax + prior + mask
    attn_mma<<<dim3((TT_TOT + 63) / 64, BB), 256, SMATT>>>(pQ2, pKT, pk2,
                                                           prior, mask, out);
}

// round 16
// speedup vs baseline: 1.1933x; 1.0202x over previous
#include <cuda_runtime.h>
#include <cuda_bf16.h>
#include <math.h>
#include <stdint.h>

#define BB 32
#define TT_TOT 1500
#define SS 256

typedef __nv_bfloat16 bf16;

// ---------------- scratch buffers (device globals) --------------------------
__device__ __align__(16) bf16 g_actT0[BB * SS * 512];
__device__ __align__(16) bf16 g_actT1[BB * SS * 512];
__device__ __align__(16) bf16 g_cT[BB * SS * 1024];
__device__ __align__(16) bf16 g_kT[BB * SS * 96];
__device__ __align__(16) bf16 g_melsT[BB * TT_TOT * 96];
__device__ __align__(16) bf16 g_q0T[(size_t)BB * TT_TOT * 192];
__device__ __align__(16) bf16 g_q1T[(size_t)BB * TT_TOT * 128];
__device__ __align__(16) bf16 g_q2T[BB * TT_TOT * 96];
// per-layer repacked weights
__device__ __align__(16) bf16 g_w0[512 * 2560];
__device__ __align__(16) bf16 g_w1[512 * 2560];
__device__ __align__(16) bf16 g_w2[512 * 2560];
__device__ __align__(16) bf16 g_w3[1024 * 1536];
__device__ __align__(16) bf16 g_w4[128 * 1024];
__device__ __align__(16) bf16 g_wq0[256 * 288];
__device__ __align__(16) bf16 g_wq1[128 * 192];
__device__ __align__(16) bf16 g_wq2[128 * 128];
__device__ __align__(16) bf16 g_zero[8];  // zero page

// ---------------- helpers ----------------------------------------------------
__device__ __forceinline__ uint32_t smem_u32(const void* p) {
    uint32_t a;
    asm("{ .reg .u64 t; cvta.to.shared.u64 t, %1; cvt.u32.u64 %0, t; }"
        : "=r"(a) : "l"(p));
    return a;
}
__device__ __forceinline__ void cp16(void* smem, const void* gmem) {
    asm volatile("cp.async.cg.shared.global [%0], [%1], 16;"
                 :: "r"(smem_u32(smem)), "l"(gmem) : "memory");
}
#define CP_COMMIT() asm volatile("cp.async.commit_group;" ::: "memory")
#define CP_WAIT0() asm volatile("cp.async.wait_group 0;" ::: "memory")
#define CP_WAIT1() asm volatile("cp.async.wait_group 1;" ::: "memory")

__device__ __forceinline__ void mma16816(float* d, const uint32_t* a,
                                         const uint32_t* b) {
    asm volatile(
        "mma.sync.aligned.m16n8k16.row.col.f32.bf16.bf16.f32 "
        "{%0,%1,%2,%3}, {%4,%5,%6,%7}, {%8,%9}, {%0,%1,%2,%3};"
        : "+f"(d[0]), "+f"(d[1]), "+f"(d[2]), "+f"(d[3])
        : "r"(a[0]), "r"(a[1]), "r"(a[2]), "r"(a[3]), "r"(b[0]), "r"(b[1]));
}
__device__ __forceinline__ void ldsm4(uint32_t& r0, uint32_t& r1, uint32_t& r2,
                                      uint32_t& r3, uint32_t addr) {
    asm volatile("ldmatrix.sync.aligned.m8n8.x4.shared.b16 {%0,%1,%2,%3}, [%4];"
                 : "=r"(r0), "=r"(r1), "=r"(r2), "=r"(r3) : "r"(addr));
}

// ---------------- embedding: actT[b][s][c] (vectorized 8/thread) ------------
__global__ void embed_kernel(const int* __restrict__ ph,
                             const float* __restrict__ emb,
                             bf16* __restrict__ out) {
    int idx = blockIdx.x * blockDim.x + threadIdx.x;
    if (idx >= BB * SS * 64) return;
    int c8 = idx & 63;
    int s = (idx >> 6) & (SS - 1);
    int b = idx >> 14;
    const float* src = emb + (size_t)ph[b * SS + s] * 512 + c8 * 8;
    float4 f0 = *(const float4*)src;
    float4 f1 = *(const float4*)(src + 4);
    bf16 v[8];
    v[0] = __float2bfloat16(f0.x); v[1] = __float2bfloat16(f0.y);
    v[2] = __float2bfloat16(f0.z); v[3] = __float2bfloat16(f0.w);
    v[4] = __float2bfloat16(f1.x); v[5] = __float2bfloat16(f1.y);
    v[6] = __float2bfloat16(f1.z); v[7] = __float2bfloat16(f1.w);
    *(uint4*)(out + (size_t)idx * 8) = *(const uint4*)v;
}

// ------- fused weight repack (all layers, one launch) -----------------------
struct PrepArgs {
    const float* src[8];
    bf16* dst[8];
    int Cout[8], Cin[8], KT[8], CINP[8], total[8];
};
__global__ __launch_bounds__(256) void prep_all(PrepArgs pa) {
    int L = blockIdx.y;
    int idx8 = (blockIdx.x * 256 + threadIdx.x) * 8;
    if (idx8 >= pa.total[L]) return;
    const int CINP = pa.CINP[L], KTv = pa.KT[L], Cin = pa.Cin[L],
              Cout = pa.Cout[L];
    const int Ktot = CINP * KTv;
    int co = idx8 / Ktot, k = idx8 - co * Ktot;
    int t = k / CINP, ci = k - t * CINP;
    const float* w = pa.src[L];
    bf16 v[8];
#pragma unroll
    for (int j = 0; j < 8; j++) {
        float f = (co < Cout && ci + j < Cin)
                      ? w[((size_t)co * Cin + ci + j) * KTv + t]
                      : 0.f;
        v[j] = __float2bfloat16(f);
    }
    *(uint4*)(pa.dst[L] + idx8) = *(const uint4*)v;
}

// ------- mels transpose: melsT[b][t][ci] (bf16, ci padded to 96) ------------
__global__ __launch_bounds__(256) void melsT_kernel(const float* __restrict__ mels,
                                                    bf16* __restrict__ melsT) {
    __shared__ float tile[32][33];
    const int b = blockIdx.z;
    const int c0 = blockIdx.y * 32;
    const int t0 = blockIdx.x * 32;
    const int tx = threadIdx.x & 31, ty = threadIdx.x >> 5;
#pragma unroll
    for (int p = 0; p < 4; p++) {
        int c = ty + p * 8;
        tile[c][tx] = (c0 + c < 80 && t0 + tx < TT_TOT)
                          ? mels[((size_t)b * 80 + c0 + c) * TT_TOT + t0 + tx]
                          : 0.f;
    }
    __syncthreads();
#pragma unroll
    for (int p = 0; p < 4; p++) {
        int t = ty + p * 8;
        if (t0 + t < TT_TOT)
            melsT[((size_t)b * TT_TOT + t0 + t) * 96 + c0 + tx] =
                __float2bfloat16(tile[tx][t]);
    }
}

// ---------------- fused conv-as-GEMM (HMMA bf16 + ldmatrix, 3-stage) --------
// Block 128co x 128s, 8 warps 2x4, warp tile 64x32, K chunk CHUNK, 3 stages.
template <int KT, int CINP, int CHUNK, bool RELU>
__global__ __launch_bounds__(256, 2) void gemm_conv(
    const bf16* __restrict__ Aw, const bf16* __restrict__ actT,
    const float* __restrict__ bias, bf16* __restrict__ outT,
    int Cout, int CS, int L) {
    constexpr int KTOT = KT * CINP;
    constexpr int NCH = KTOT / CHUNK;
    constexpr int PAD = KT / 2;
    constexpr int RP = CHUNK + 8;
    constexpr int UPR = CHUNK / 8;
    constexpr int KKN = CHUNK / 16;
    constexpr int STG = 2 * 128 * RP;   // elems per stage (A then B)
    extern __shared__ __align__(16) bf16 dyn[];

    const int tid = threadIdx.x;
    const int wid = tid >> 5, lane = tid & 31;
    const int wm = wid >> 2, wn = wid & 3;
    const int lr = lane >> 2, lc = (lane & 3) * 2;
    const int b = blockIdx.z, co0 = blockIdx.y * 128, s0 = blockIdx.x * 128;

    const bf16* gA = Aw + (size_t)co0 * KTOT;
    const bf16* actB = actT + (size_t)b * L * CINP;

    const int lmA_off = ((lane & 7) + ((lane >> 3) & 1) * 8) * RP +
                        (lane >> 4) * 8;
    const int lmB_off = ((lane & 7) + ((lane >> 4) & 1) * 8) * RP +
                        ((lane >> 3) & 1) * 8;
    const uint32_t aLm0 = smem_u32(dyn + (wm * 64) * RP + lmA_off);
    const uint32_t bLm0 = smem_u32(dyn + 128 * RP + (wn * 32) * RP + lmB_off);
    constexpr uint32_t STGB = STG * 2;  // stage stride bytes

    float acc[4][4][4];
#pragma unroll
    for (int i = 0; i < 4; i++)
#pragma unroll
        for (int j = 0; j < 4; j++)
#pragma unroll
            for (int v = 0; v < 4; v++) acc[i][j][v] = 0.f;

    auto load_chunk = [&](int stg, int ch) {
        const int k0 = ch * CHUNK;
        bf16* dA = dyn + stg * STG;
        bf16* dB = dA + 128 * RP;
#pragma unroll
        for (int n = 0; n < UPR / 2; n++) {
            int i = tid + n * 256;
            int row = i / UPR, u = i % UPR;
            cp16(dA + row * RP + u * 8, gA + (size_t)row * KTOT + k0 + u * 8);
        }
#pragma unroll
        for (int n = 0; n < UPR / 2; n++) {
            int i = tid + n * 256;
            int row = i / UPR, u = i % UPR;
            int k = k0 + u * 8;
            int t = k / CINP;
            int ci = k - t * CINP;
            int gs = s0 + row + t - PAD;
            const bf16* src = (gs >= 0 && gs < L)
                                  ? actB + (size_t)gs * CINP + ci
                                  : g_zero;
            cp16(dB + row * RP + u * 8, src);
        }
        CP_COMMIT();
    };

    load_chunk(0, 0);
    load_chunk(1, 1);

    int st = 0, st2 = 2;
    for (int ch = 0; ch < NCH; ch++) {
        if (ch + 1 < NCH) { CP_WAIT1(); } else { CP_WAIT0(); }
        __syncthreads();
        if (ch + 2 < NCH) load_chunk(st2, ch + 2);
        const uint32_t aB = aLm0 + st * STGB;
        const uint32_t bB = bLm0 + st * STGB;
#pragma unroll
        for (int kk = 0; kk < KKN; kk++) {
            uint32_t af[4][4];
#pragma unroll
            for (int im = 0; im < 4; im++)
                ldsm4(af[im][0], af[im][1], af[im][2], af[im][3],
                      aB + (im * 16 * RP + kk * 16) * 2);
            uint32_t bfr[4][2];
#pragma unroll
            for (int h = 0; h < 2; h++)
                ldsm4(bfr[2 * h][0], bfr[2 * h][1], bfr[2 * h + 1][0],
                      bfr[2 * h + 1][1], bB + (h * 16 * RP + kk * 16) * 2);
#pragma unroll
            for (int im = 0; im < 4; im++)
#pragma unroll
                for (int in = 0; in < 4; in++)
                    mma16816(acc[im][in], af[im], bfr[in]);
        }
        st = (st == 2) ? 0 : st + 1;
        st2 = (st2 == 2) ? 0 : st2 + 1;
    }
    __syncthreads();  // all reads done before ep overwrite

    // transposed epilogue: acc -> ep[s][co] (bf16, stride 72) -> stores
    bf16* ep = dyn;  // 128 x 72 bf16
#pragma unroll
    for (int c = 0; c < 2; c++) {
        if (wm == c) {
#pragma unroll
            for (int im = 0; im < 4; im++) {
                int co_loc = im * 16 + lr;
                int gco = co0 + c * 64 + co_loc;
                float b0v = (gco < Cout) ? bias[gco] : 0.f;
                float b1v = (gco + 8 < Cout) ? bias[gco + 8] : 0.f;
#pragma unroll
                for (int in = 0; in < 4; in++) {
                    int sl = wn * 32 + in * 8 + lc;
                    float* d = acc[im][in];
                    float v0 = d[0] + b0v, v1 = d[1] + b0v;
                    float v2 = d[2] + b1v, v3 = d[3] + b1v;
                    if (RELU) {
                        v0 = fmaxf(v0, 0.f); v1 = fmaxf(v1, 0.f);
                        v2 = fmaxf(v2, 0.f); v3 = fmaxf(v3, 0.f);
                    }
                    ep[sl * 72 + co_loc] = __float2bfloat16(v0);
                    ep[(sl + 1) * 72 + co_loc] = __float2bfloat16(v1);
                    ep[sl * 72 + co_loc + 8] = __float2bfloat16(v2);
                    ep[(sl + 1) * 72 + co_loc + 8] = __float2bfloat16(v3);
                }
            }
        }
        __syncthreads();
        int w = CS - (co0 + c * 64);
        if (w > 64) w = 64;
        if (w > 0) {
            int vpr = w >> 3;
            int tot = 128 * vpr;
            for (int idx = tid; idx < tot; idx += 256) {
                int s = idx / vpr, v = idx - s * vpr;
                if (s0 + s < L)
                    *(uint4*)(outT + ((size_t)b * L + s0 + s) * CS + co0 +
                              c * 64 + v * 8) = *(const uint4*)(ep + s * 72 + v * 8);
            }
        }
        __syncthreads();
    }
}

// ---------------- HMMA attention: qk + log_softmax + prior + mask -----------
// k2 computed in-kernel from staged K tile (fused; k2_kernel removed).
// K-dim = 80 real channels (81..95 are exact zero padding; skipped exactly).
__global__ __launch_bounds__(256) void attn_mma(
    const bf16* __restrict__ q2T, const bf16* __restrict__ kT,
    const float* __restrict__ prior, const int* __restrict__ mask,
    float* __restrict__ out) {
    constexpr float TEMP = 0.0005f;
    constexpr int RP = 104;
    extern __shared__ __align__(16) bf16 dynA[];
    bf16* sQ = dynA;
    bf16* sK = dynA + 64 * RP;
    float* k2s = (float*)(dynA + (64 + 256) * RP);
    float* redM = k2s + 256;
    float* redS = redM + 256;
    float* lseS = redS + 256;

    const int tid = threadIdx.x;
    const int wid = tid >> 5, lane = tid & 31;
    const int wm = wid >> 2, wn = wid & 3;
    const int lr = lane >> 2, qq = lane & 3, lc = qq * 2;
    const int b = blockIdx.y, t0 = blockIdx.x * 64;

#pragma unroll
    for (int n = 0; n < 3; n++) {
        int i = tid + n * 256;
        int row = i / 12, u = i % 12;
        int gt = t0 + row;
        const bf16* src = (gt < TT_TOT)
                              ? q2T + ((size_t)b * TT_TOT + gt) * 96 + u * 8
                              : g_zero;
        cp16(sQ + row * RP + u * 8, src);
    }
#pragma unroll
    for (int n = 0; n < 12; n++) {
        int i = tid + n * 256;
        int row = i / 12, u = i % 12;
        cp16(sK + row * RP + u * 8, kT + ((size_t)b * SS + row) * 96 + u * 8);
    }
    CP_COMMIT();
    CP_WAIT0();
    __syncthreads();

    // fused k2: thread s sums squares of its K row (80 real channels)
    {
        const uint32_t* row = (const uint32_t*)(sK + tid * RP);
        float sum = 0.f;
#pragma unroll
        for (int u = 0; u < 40; u++) {
            float2 f = __bfloat1622float2(*(const __nv_bfloat162*)&row[u]);
            sum = fmaf(f.x, f.x, fmaf(f.y, f.y, sum));
        }
        k2s[tid] = sum;
    }
    __syncthreads();

    const int lmA_off = ((lane & 7) + ((lane >> 3) & 1) * 8) * RP +
                        (lane >> 4) * 8;
    const int lmB_off = ((lane & 7) + ((lane >> 4) & 1) * 8) * RP +
                        ((lane >> 3) & 1) * 8;
    const uint32_t aB = smem_u32(sQ + (wm * 32) * RP + lmA_off);
    const uint32_t bB = smem_u32(sK + (wn * 64) * RP + lmB_off);

    float acc[2][8][4];
#pragma unroll
    for (int i = 0; i < 2; i++)
#pragma unroll
        for (int j = 0; j < 8; j++)
#pragma unroll
            for (int v = 0; v < 4; v++) acc[i][j][v] = 0.f;

    // K = 80: kk = 5 covers channels 80..95 which are exact zeros -> skipped
#pragma unroll
    for (int kk = 0; kk < 5; kk++) {
        uint32_t af[2][4];
#pragma unroll
        for (int im = 0; im < 2; im++)
            ldsm4(af[im][0], af[im][1], af[im][2], af[im][3],
                  aB + (im * 16 * RP + kk * 16) * 2);
        uint32_t bfr[8][2];
#pragma unroll
        for (int h = 0; h < 4; h++)
            ldsm4(bfr[2 * h][0], bfr[2 * h][1], bfr[2 * h + 1][0],
                  bfr[2 * h + 1][1], bB + (h * 16 * RP + kk * 16) * 2);
#pragma unroll
        for (int im = 0; im < 2; im++)
#pragma unroll
            for (int in = 0; in < 8; in++)
                mma16816(acc[im][in], af[im], bfr[in]);
    }

#pragma unroll
    for (int im = 0; im < 2; im++)
#pragma unroll
        for (int in = 0; in < 8; in++) {
            int s = wn * 64 + in * 8 + lc;
            float2 kv = *(float2*)&k2s[s];
            acc[im][in][0] = TEMP * (2.f * acc[im][in][0] - kv.x);
            acc[im][in][1] = TEMP * (2.f * acc[im][in][1] - kv.y);
            acc[im][in][2] = TEMP * (2.f * acc[im][in][2] - kv.x);
            acc[im][in][3] = TEMP * (2.f * acc[im][in][3] - kv.y);
        }

#pragma unroll
    for (int im = 0; im < 2; im++)
#pragma unroll
        for (int h = 0; h < 2; h++) {
            float m = -INFINITY, se = 0.f;
#pragma unroll
            for (int in = 0; in < 8; in++) {
                float v0 = acc[im][in][2 * h], v1 = acc[im][in][2 * h + 1];
                float M = fmaxf(m, fmaxf(v0, v1));
                se = se * __expf(m - M) + __expf(v0 - M) + __expf(v1 - M);
                m = M;
            }
#pragma unroll
            for (int o = 1; o <= 2; o <<= 1) {
                float m2 = __shfl_xor_sync(~0u, m, o);
                float s2 = __shfl_xor_sync(~0u, se, o);
                float M = fmaxf(m, m2);
                se = se * __expf(m - M) + s2 * __expf(m2 - M);
                m = M;
            }
            if (qq == 0) {
                int row = wm * 32 + im * 16 + h * 8 + lr;
                redM[wn * 64 + row] = m;
                redS[wn * 64 + row] = se;
            }
        }
    __syncthreads();
    if (tid < 64) {
        float M = redM[tid], SE = redS[tid];
#pragma unroll
        for (int i = 1; i < 4; i++) {
            float mi = redM[i * 64 + tid], si = redS[i * 64 + tid];
            float Mn = fmaxf(M, mi);
            SE = SE * __expf(M - Mn) + si * __expf(mi - Mn);
            M = Mn;
        }
        lseS[tid] = M + __logf(SE);
    }
    __syncthreads();

#pragma unroll
    for (int im = 0; im < 2; im++)
#pragma unroll
        for (int h = 0; h < 2; h++) {
            int row = wm * 32 + im * 16 + h * 8 + lr;
            int t = t0 + row;
            if (t < TT_TOT) {
                float lse = lseS[row];
                size_t base = ((size_t)b * TT_TOT + t) * SS;
#pragma unroll
                for (int in = 0; in < 8; in++) {
                    int s = wn * 64 + in * 8 + lc;
                    size_t o = base + s;
                    float2 pr = *(const float2*)&prior[o];
                    int2 mk = *(const int2*)&mask[o];
                    float v0 = acc[im][in][2 * h] - lse + __logf(pr.x + 1e-8f);
                    float v1 = acc[im][in][2 * h + 1] - lse + __logf(pr.y + 1e-8f);
                    float2 res;
                    res.x = mk.x ? v0 : -INFINITY;
                    res.y = mk.y ? v1 : -INFINITY;
                    *(float2*)&out[o] = res;
                }
            }
        }
}

// ---------------- launch ----------------------------------------------------
extern "C" void kernel_launch(void* const* d_in, const int* in_sizes, int n_in,
                              void* d_out, int out_size) {
    const int* phonemes = (const int*)d_in[0];
    const float* mels = (const float*)d_in[1];
    const int* mask = (const int*)d_in[2];
    const float* prior = (const float*)d_in[3];
    const float* emb = (const float*)d_in[4];
    const float* kw[5] = {(const float*)d_in[5], (const float*)d_in[7],
                          (const float*)d_in[9], (const float*)d_in[11],
                          (const float*)d_in[13]};
    const float* kb[5] = {(const float*)d_in[6], (const float*)d_in[8],
                          (const float*)d_in[10], (const float*)d_in[12],
                          (const float*)d_in[14]};
    const float* qw[3] = {(const float*)d_in[15], (const float*)d_in[17],
                          (const float*)d_in[19]};
    const float* qb[3] = {(const float*)d_in[16], (const float*)d_in[18],
                          (const float*)d_in[20]};
    float* out = (float*)d_out;

    bf16 *pA0, *pA1, *pCT, *pKT, *pMT, *pQ0, *pQ1, *pQ2;
    bf16* pw[8];
    cudaGetSymbolAddress((void**)&pA0, g_actT0);
    cudaGetSymbolAddress((void**)&pA1, g_actT1);
    cudaGetSymbolAddress((void**)&pCT, g_cT);
    cudaGetSymbolAddress((void**)&pKT, g_kT);
    cudaGetSymbolAddress((void**)&pMT, g_melsT);
    cudaGetSymbolAddress((void**)&pQ0, g_q0T);
    cudaGetSymbolAddress((void**)&pQ1, g_q1T);
    cudaGetSymbolAddress((void**)&pQ2, g_q2T);
    cudaGetSymbolAddress((void**)&pw[0], g_w0);
    cudaGetSymbolAddress((void**)&pw[1], g_w1);
    cudaGetSymbolAddress((void**)&pw[2], g_w2);
    cudaGetSymbolAddress((void**)&pw[3], g_w3);
    cudaGetSymbolAddress((void**)&pw[4], g_w4);
    cudaGetSymbolAddress((void**)&pw[5], g_wq0);
    cudaGetSymbolAddress((void**)&pw[6], g_wq1);
    cudaGetSymbolAddress((void**)&pw[7], g_wq2);

    // dynamic smem opt-in (3-stage ring)
    const int SM64 = 3 * 2 * 128 * 72 * 2;   // 110592
    const int SM32 = 3 * 2 * 128 * 40 * 2;   // 61440
    const int SMATT = (64 + 256) * 104 * 2 + (256 * 3 + 64) * 4;  // 69888
    cudaFuncSetAttribute(gemm_conv<5, 512, 64, true>,
                         cudaFuncAttributeMaxDynamicSharedMemorySize, SM64);
    cudaFuncSetAttribute(gemm_conv<3, 512, 64, true>,
                         cudaFuncAttributeMaxDynamicSharedMemorySize, SM64);
    cudaFuncSetAttribute(gemm_conv<1, 1024, 64, false>,
                         cudaFuncAttributeMaxDynamicSharedMemorySize, SM64);
    cudaFuncSetAttribute(gemm_conv<3, 96, 32, true>,
                         cudaFuncAttributeMaxDynamicSharedMemorySize, SM32);
    cudaFuncSetAttribute(gemm_conv<1, 192, 64, true>,
                         cudaFuncAttributeMaxDynamicSharedMemorySize, SM64);
    cudaFuncSetAttribute(gemm_conv<1, 128, 64, false>,
                         cudaFuncAttributeMaxDynamicSharedMemorySize, SM64);
    cudaFuncSetAttribute(attn_mma,
                         cudaFuncAttributeMaxDynamicSharedMemorySize, SMATT);

    // fork-join side stream (created fresh per invocation; kernel_launch runs
    // only for correctness + capture, so no unbounded resource growth)
    cudaStream_t sQ;
    cudaStreamCreateWithFlags(&sQ, cudaStreamNonBlocking);
    cudaEvent_t evFork, evPrep, evQ;
    cudaEventCreateWithFlags(&evFork, cudaEventDisableTiming);
    cudaEventCreateWithFlags(&evPrep, cudaEventDisableTiming);
    cudaEventCreateWithFlags(&evQ, cudaEventDisableTiming);

    // fork: side stream joins the (possibly capturing) legacy stream
    cudaEventRecord(evFork, 0);
    cudaStreamWaitEvent(sQ, evFork, 0);

    // main: embedding; side: mels transpose
    embed_kernel<<<(BB * SS * 64 + 255) / 256, 256>>>(phonemes, emb, pA0);
    melsT_kernel<<<dim3(47, 3, BB), 256, 0, sQ>>>(mels, pMT);

    // all weight repacks in one launch (main)
    PrepArgs pa;
    const int CoutA[8] = {512, 512, 512, 1024, 80, 160, 80, 80};
    const int CinA[8] = {512, 512, 512, 512, 1024, 80, 160, 80};
    const int KTA[8] = {5, 5, 5, 3, 1, 3, 1, 1};
    const int CINPA[8] = {512, 512, 512, 512, 1024, 96, 192, 128};
    const int RPAD[8] = {512, 512, 512, 1024, 128, 256, 128, 128};
    const float* srcs[8] = {kw[0], kw[1], kw[2], kw[3], kw[4],
                            qw[0], qw[1], qw[2]};
    for (int i = 0; i < 8; i++) {
        pa.src[i] = srcs[i];
        pa.dst[i] = pw[i];
        pa.Cout[i] = CoutA[i];
        pa.Cin[i] = CinA[i];
        pa.KT[i] = KTA[i];
        pa.CINP[i] = CINPA[i];
        pa.total[i] = RPAD[i] * KTA[i] * CINPA[i];
    }
    prep_all<<<dim3(768, 8), 256>>>(pa);
    cudaEventRecord(evPrep, 0);

    // ---- query encoder on side stream (fills idle SM slots of key chain) ---
    cudaStreamWaitEvent(sQ, evPrep, 0);
    gemm_conv<3, 96, 32, true><<<dim3(12, 2, BB), 256, SM32, sQ>>>(
        pw[5], pMT, qb[0], pQ0, 160, 192, TT_TOT);
    gemm_conv<1, 192, 64, true><<<dim3(12, 1, BB), 256, SM64, sQ>>>(
        pw[6], pQ0, qb[1], pQ1, 80, 128, TT_TOT);
    gemm_conv<1, 128, 64, false><<<dim3(12, 1, BB), 256, SM64, sQ>>>(
        pw[7], pQ1, qb[2], pQ2, 80, 96, TT_TOT);
    cudaEventRecord(evQ, sQ);

    // ---- key encoder on main stream ----
    gemm_conv<5, 512, 64, true><<<dim3(2, 4, BB), 256, SM64>>>(
        pw[0], pA0, kb[0], pA1, 512, 512, SS);
    gemm_conv<5, 512, 64, true><<<dim3(2, 4, BB), 256, SM64>>>(
        pw[1], pA1, kb[1], pA0, 512, 512, SS);
    gemm_conv<5, 512, 64, true><<<dim3(2, 4, BB), 256, SM64>>>(
        pw[2], pA0, kb[2], pA1, 512, 512, SS);
    gemm_conv<3, 512, 64, true><<<dim3(2, 8, BB), 256, SM64>>>(
        pw[3], pA1, kb[3], pCT, 1024, 1024, SS);
    gemm_conv<1, 1024, 64, false><<<dim3(2, 1, BB), 256, SM64>>>(
        pw[4], pCT, kb[4], pKT, 80, 96, SS);

    // join: attention needs the query path
    cudaStreamWaitEvent(0, evQ, 0);

    // HMMA attention + fused k2 + log_softmax + prior + mask
    attn_mma<<<dim3((TT_TOT + 63) / 64, BB), 256, SMATT>>>(pQ2, pKT, prior,
                                                           mask, out);
}

// round 17
// speedup vs baseline: 1.3338x; 1.1178x over previous
#include <cuda_runtime.h>
#include <cuda_bf16.h>
#include <math.h>
#include <stdint.h>

#define BB 32
#define TT_TOT 1500
#define SS 256

typedef __nv_bfloat16 bf16;

// ---------------- scratch buffers (device globals) --------------------------
__device__ __align__(16) bf16 g_actT0[BB * SS * 512];   // also holds T table
__device__ __align__(16) bf16 g_actT1[BB * SS * 512];
__device__ __align__(16) bf16 g_cT[BB * SS * 1024];
__device__ __align__(16) bf16 g_kT[BB * SS * 96];
__device__ __align__(16) bf16 g_melsT[BB * TT_TOT * 96];
__device__ __align__(16) bf16 g_q0T[(size_t)BB * TT_TOT * 192];
__device__ __align__(16) bf16 g_q1T[(size_t)BB * TT_TOT * 128];
__device__ __align__(16) bf16 g_q2T[BB * TT_TOT * 96];
// repacked weights
__device__ __align__(16) bf16 g_wT[2560 * 512];   // layer0 per-tap weights
__device__ __align__(16) bf16 g_embB[128 * 512];  // emb -> bf16 (padded rows)
__device__ __align__(16) bf16 g_w1[512 * 2560];
__device__ __align__(16) bf16 g_w2[512 * 2560];
__device__ __align__(16) bf16 g_w3[1024 * 1536];
__device__ __align__(16) bf16 g_w4[128 * 1024];
__device__ __align__(16) bf16 g_wq0[256 * 288];
__device__ __align__(16) bf16 g_wq1[128 * 192];
__device__ __align__(16) bf16 g_wq2[128 * 128];
__device__ float g_bias0[2560];                    // zeros (T-GEMM bias)
__device__ __align__(16) bf16 g_zero[8];           // zero page

// ---------------- helpers ----------------------------------------------------
__device__ __forceinline__ uint32_t smem_u32(const void* p) {
    uint32_t a;
    asm("{ .reg .u64 t; cvta.to.shared.u64 t, %1; cvt.u32.u64 %0, t; }"
        : "=r"(a) : "l"(p));
    return a;
}
__device__ __forceinline__ void cp16(void* smem, const void* gmem) {
    asm volatile("cp.async.cg.shared.global [%0], [%1], 16;"
                 :: "r"(smem_u32(smem)), "l"(gmem) : "memory");
}
#define CP_COMMIT() asm volatile("cp.async.commit_group;" ::: "memory")
#define CP_WAIT0() asm volatile("cp.async.wait_group 0;" ::: "memory")
#define CP_WAIT1() asm volatile("cp.async.wait_group 1;" ::: "memory")

__device__ __forceinline__ void mma16816(float* d, const uint32_t* a,
                                         const uint32_t* b) {
    asm volatile(
        "mma.sync.aligned.m16n8k16.row.col.f32.bf16.bf16.f32 "
        "{%0,%1,%2,%3}, {%4,%5,%6,%7}, {%8,%9}, {%0,%1,%2,%3};"
        : "+f"(d[0]), "+f"(d[1]), "+f"(d[2]), "+f"(d[3])
        : "r"(a[0]), "r"(a[1]), "r"(a[2]), "r"(a[3]), "r"(b[0]), "r"(b[1]));
}
__device__ __forceinline__ void ldsm4(uint32_t& r0, uint32_t& r1, uint32_t& r2,
                                      uint32_t& r3, uint32_t addr) {
    asm volatile("ldmatrix.sync.aligned.m8n8.x4.shared.b16 {%0,%1,%2,%3}, [%4];"
                 : "=r"(r0), "=r"(r1), "=r"(r2), "=r"(r3) : "r"(addr));
}

// ------- fused weight repack (all layers + emb + per-tap layer0), 9 slots ---
struct PrepArgs {
    const float* src[9];
    bf16* dst[9];
    int Cout[9], Cin[9], KT[9], CINP[9], total[9], mode[9];
};
__global__ __launch_bounds__(256) void prep_all(PrepArgs pa) {
    int L = blockIdx.y;
    int idx8 = (blockIdx.x * 256 + threadIdx.x) * 8;
    if (idx8 >= pa.total[L]) return;
    const float* w = pa.src[L];
    bf16 v[8];
    if (pa.mode[L] == 1) {
        // layer0 per-tap: dst[t*512+co][ci] = kw0[co][ci][t]
        int r = idx8 >> 9;           // row (0..2559)
        int ci = idx8 & 511;
        int t = r >> 9;              // r / 512
        int co0 = r & 511;
#pragma unroll
        for (int j = 0; j < 8; j++)
            v[j] = __float2bfloat16(w[((size_t)(co0 * 512 + ci + j)) * 5 + t]);
    } else {
        const int CINP = pa.CINP[L], KTv = pa.KT[L], Cin = pa.Cin[L],
                  Cout = pa.Cout[L];
        const int Ktot = CINP * KTv;
        int co = idx8 / Ktot, k = idx8 - co * Ktot;
        int t = k / CINP, ci = k - t * CINP;
#pragma unroll
        for (int j = 0; j < 8; j++) {
            float f = (co < Cout && ci + j < Cin)
                          ? w[((size_t)co * Cin + ci + j) * KTv + t]
                          : 0.f;
            v[j] = __float2bfloat16(f);
        }
    }
    *(uint4*)(pa.dst[L] + idx8) = *(const uint4*)v;
}

// ------- layer0 via table gather: out[b][s][co]=relu(bias+Σ_t T[v_t][t*512+co])
__global__ __launch_bounds__(256) void layer0_kernel(
    const bf16* __restrict__ T, const int* __restrict__ ph,
    const float* __restrict__ bias, bf16* __restrict__ out) {
    __shared__ int phw[68];
    const int b = blockIdx.y, s0 = blockIdx.x * 64;
    if (threadIdx.x < 68) {
        int s = s0 + (int)threadIdx.x - 2;
        phw[threadIdx.x] = (s >= 0 && s < SS) ? ph[b * SS + s] : -1;
    }
    __syncthreads();
    for (int it = threadIdx.x; it < 64 * 64; it += 256) {
        int sl = it >> 6, c8 = it & 63;
        float acc[8];
        const float4* bp = (const float4*)(bias + c8 * 8);
        float4 b0 = bp[0], b1 = bp[1];
        acc[0] = b0.x; acc[1] = b0.y; acc[2] = b0.z; acc[3] = b0.w;
        acc[4] = b1.x; acc[5] = b1.y; acc[6] = b1.z; acc[7] = b1.w;
#pragma unroll
        for (int t = 0; t < 5; t++) {
            int v = phw[sl + t];
            if (v >= 0) {
                uint4 u = *(const uint4*)(T + (size_t)v * 2560 + t * 512 + c8 * 8);
                const __nv_bfloat162* h = (const __nv_bfloat162*)&u;
#pragma unroll
                for (int j = 0; j < 4; j++) {
                    float2 f = __bfloat1622float2(h[j]);
                    acc[2 * j] += f.x;
                    acc[2 * j + 1] += f.y;
                }
            }
        }
        bf16 vv[8];
#pragma unroll
        for (int j = 0; j < 8; j++)
            vv[j] = __float2bfloat16(fmaxf(acc[j], 0.f));
        *(uint4*)(out + ((size_t)b * SS + s0 + sl) * 512 + c8 * 8) =
            *(const uint4*)vv;
    }
}

// ------- mels transpose: melsT[b][t][ci] (bf16, ci padded to 96) ------------
__global__ __launch_bounds__(256) void melsT_kernel(const float* __restrict__ mels,
                                                    bf16* __restrict__ melsT) {
    __shared__ float tile[32][33];
    const int b = blockIdx.z;
    const int c0 = blockIdx.y * 32;
    const int t0 = blockIdx.x * 32;
    const int tx = threadIdx.x & 31, ty = threadIdx.x >> 5;
#pragma unroll
    for (int p = 0; p < 4; p++) {
        int c = ty + p * 8;
        tile[c][tx] = (c0 + c < 80 && t0 + tx < TT_TOT)
                          ? mels[((size_t)b * 80 + c0 + c) * TT_TOT + t0 + tx]
                          : 0.f;
    }
    __syncthreads();
#pragma unroll
    for (int p = 0; p < 4; p++) {
        int t = ty + p * 8;
        if (t0 + t < TT_TOT)
            melsT[((size_t)b * TT_TOT + t0 + t) * 96 + c0 + tx] =
                __float2bfloat16(tile[tx][t]);
    }
}

// ---------------- fused conv-as-GEMM (HMMA bf16 + ldmatrix, 3-stage) --------
// Block 128co x 128s, 8 warps 2x4, warp tile 64x32, K chunk CHUNK, 3 stages.
template <int KT, int CINP, int CHUNK, bool RELU>
__global__ __launch_bounds__(256, 2) void gemm_conv(
    const bf16* __restrict__ Aw, const bf16* __restrict__ actT,
    const float* __restrict__ bias, bf16* __restrict__ outT,
    int Cout, int CS, int L) {
    constexpr int KTOT = KT * CINP;
    constexpr int NCH = KTOT / CHUNK;
    constexpr int PAD = KT / 2;
    constexpr int RP = CHUNK + 8;
    constexpr int UPR = CHUNK / 8;
    constexpr int KKN = CHUNK / 16;
    constexpr int STG = 2 * 128 * RP;   // elems per stage (A then B)
    extern __shared__ __align__(16) bf16 dyn[];

    const int tid = threadIdx.x;
    const int wid = tid >> 5, lane = tid & 31;
    const int wm = wid >> 2, wn = wid & 3;
    const int lr = lane >> 2, lc = (lane & 3) * 2;
    const int b = blockIdx.z, co0 = blockIdx.y * 128, s0 = blockIdx.x * 128;

    const bf16* gA = Aw + (size_t)co0 * KTOT;
    const bf16* actB = actT + (size_t)b * L * CINP;

    const int lmA_off = ((lane & 7) + ((lane >> 3) & 1) * 8) * RP +
                        (lane >> 4) * 8;
    const int lmB_off = ((lane & 7) + ((lane >> 4) & 1) * 8) * RP +
                        ((lane >> 3) & 1) * 8;
    const uint32_t aLm0 = smem_u32(dyn + (wm * 64) * RP + lmA_off);
    const uint32_t bLm0 = smem_u32(dyn + 128 * RP + (wn * 32) * RP + lmB_off);
    constexpr uint32_t STGB = STG * 2;  // stage stride bytes

    float acc[4][4][4];
#pragma unroll
    for (int i = 0; i < 4; i++)
#pragma unroll
        for (int j = 0; j < 4; j++)
#pragma unroll
            for (int v = 0; v < 4; v++) acc[i][j][v] = 0.f;

    auto load_chunk = [&](int stg, int ch) {
        const int k0 = ch * CHUNK;
        bf16* dA = dyn + stg * STG;
        bf16* dB = dA + 128 * RP;
#pragma unroll
        for (int n = 0; n < UPR / 2; n++) {
            int i = tid + n * 256;
            int row = i / UPR, u = i % UPR;
            cp16(dA + row * RP + u * 8, gA + (size_t)row * KTOT + k0 + u * 8);
        }
#pragma unroll
        for (int n = 0; n < UPR / 2; n++) {
            int i = tid + n * 256;
            int row = i / UPR, u = i % UPR;
            int k = k0 + u * 8;
            int t = k / CINP;
            int ci = k - t * CINP;
            int gs = s0 + row + t - PAD;
            const bf16* src = (gs >= 0 && gs < L)
                                  ? actB + (size_t)gs * CINP + ci
                                  : g_zero;
            cp16(dB + row * RP + u * 8, src);
        }
        CP_COMMIT();
    };

    load_chunk(0, 0);
    load_chunk(1, 1);

    int st = 0, st2 = 2;
    for (int ch = 0; ch < NCH; ch++) {
        if (ch + 1 < NCH) { CP_WAIT1(); } else { CP_WAIT0(); }
        __syncthreads();
        if (ch + 2 < NCH) load_chunk(st2, ch + 2);
        const uint32_t aB = aLm0 + st * STGB;
        const uint32_t bB = bLm0 + st * STGB;
#pragma unroll
        for (int kk = 0; kk < KKN; kk++) {
            uint32_t af[4][4];
#pragma unroll
            for (int im = 0; im < 4; im++)
                ldsm4(af[im][0], af[im][1], af[im][2], af[im][3],
                      aB + (im * 16 * RP + kk * 16) * 2);
            uint32_t bfr[4][2];
#pragma unroll
            for (int h = 0; h < 2; h++)
                ldsm4(bfr[2 * h][0], bfr[2 * h][1], bfr[2 * h + 1][0],
                      bfr[2 * h + 1][1], bB + (h * 16 * RP + kk * 16) * 2);
#pragma unroll
            for (int im = 0; im < 4; im++)
#pragma unroll
                for (int in = 0; in < 4; in++)
                    mma16816(acc[im][in], af[im], bfr[in]);
        }
        st = (st == 2) ? 0 : st + 1;
        st2 = (st2 == 2) ? 0 : st2 + 1;
    }
    __syncthreads();  // all reads done before ep overwrite

    // transposed epilogue: acc -> ep[s][co] (bf16, stride 72) -> stores
    bf16* ep = dyn;  // 128 x 72 bf16
#pragma unroll
    for (int c = 0; c < 2; c++) {
        if (wm == c) {
#pragma unroll
            for (int im = 0; im < 4; im++) {
                int co_loc = im * 16 + lr;
                int gco = co0 + c * 64 + co_loc;
                float b0v = (gco < Cout) ? bias[gco] : 0.f;
                float b1v = (gco + 8 < Cout) ? bias[gco + 8] : 0.f;
#pragma unroll
                for (int in = 0; in < 4; in++) {
                    int sl = wn * 32 + in * 8 + lc;
                    float* d = acc[im][in];
                    float v0 = d[0] + b0v, v1 = d[1] + b0v;
                    float v2 = d[2] + b1v, v3 = d[3] + b1v;
                    if (RELU) {
                        v0 = fmaxf(v0, 0.f); v1 = fmaxf(v1, 0.f);
                        v2 = fmaxf(v2, 0.f); v3 = fmaxf(v3, 0.f);
                    }
                    ep[sl * 72 + co_loc] = __float2bfloat16(v0);
                    ep[(sl + 1) * 72 + co_loc] = __float2bfloat16(v1);
                    ep[sl * 72 + co_loc + 8] = __float2bfloat16(v2);
                    ep[(sl + 1) * 72 + co_loc + 8] = __float2bfloat16(v3);
                }
            }
        }
        __syncthreads();
        int w = CS - (co0 + c * 64);
        if (w > 64) w = 64;
        if (w > 0) {
            int vpr = w >> 3;
            int tot = 128 * vpr;
            for (int idx = tid; idx < tot; idx += 256) {
                int s = idx / vpr, v = idx - s * vpr;
                if (s0 + s < L)
                    *(uint4*)(outT + ((size_t)b * L + s0 + s) * CS + co0 +
                              c * 64 + v * 8) = *(const uint4*)(ep + s * 72 + v * 8);
            }
        }
        __syncthreads();
    }
}

// ---------------- HMMA attention: qk + fused k2 + log_softmax + prior + mask
__global__ __launch_bounds__(256) void attn_mma(
    const bf16* __restrict__ q2T, const bf16* __restrict__ kT,
    const float* __restrict__ prior, const int* __restrict__ mask,
    float* __restrict__ out) {
    constexpr float TEMP = 0.0005f;
    constexpr int RP = 104;
    extern __shared__ __align__(16) bf16 dynA[];
    bf16* sQ = dynA;
    bf16* sK = dynA + 64 * RP;
    float* k2s = (float*)(dynA + (64 + 256) * RP);
    float* redM = k2s + 256;
    float* redS = redM + 256;
    float* lseS = redS + 256;

    const int tid = threadIdx.x;
    const int wid = tid >> 5, lane = tid & 31;
    const int wm = wid >> 2, wn = wid & 3;
    const int lr = lane >> 2, qq = lane & 3, lc = qq * 2;
    const int b = blockIdx.y, t0 = blockIdx.x * 64;

#pragma unroll
    for (int n = 0; n < 3; n++) {
        int i = tid + n * 256;
        int row = i / 12, u = i % 12;
        int gt = t0 + row;
        const bf16* src = (gt < TT_TOT)
                              ? q2T + ((size_t)b * TT_TOT + gt) * 96 + u * 8
                              : g_zero;
        cp16(sQ + row * RP + u * 8, src);
    }
#pragma unroll
    for (int n = 0; n < 12; n++) {
        int i = tid + n * 256;
        int row = i / 12, u = i % 12;
        cp16(sK + row * RP + u * 8, kT + ((size_t)b * SS + row) * 96 + u * 8);
    }
    CP_COMMIT();
    CP_WAIT0();
    __syncthreads();

    // fused k2: thread s sums squares of its K row (80 real channels)
    {
        const uint32_t* row = (const uint32_t*)(sK + tid * RP);
        float sum = 0.f;
#pragma unroll
        for (int u = 0; u < 40; u++) {
            float2 f = __bfloat1622float2(*(const __nv_bfloat162*)&row[u]);
            sum = fmaf(f.x, f.x, fmaf(f.y, f.y, sum));
        }
        k2s[tid] = sum;
    }
    __syncthreads();

    const int lmA_off = ((lane & 7) + ((lane >> 3) & 1) * 8) * RP +
                        (lane >> 4) * 8;
    const int lmB_off = ((lane & 7) + ((lane >> 4) & 1) * 8) * RP +
                        ((lane >> 3) & 1) * 8;
    const uint32_t aB = smem_u32(sQ + (wm * 32) * RP + lmA_off);
    const uint32_t bB = smem_u32(sK + (wn * 64) * RP + lmB_off);

    float acc[2][8][4];
#pragma unroll
    for (int i = 0; i < 2; i++)
#pragma unroll
        for (int j = 0; j < 8; j++)
#pragma unroll
            for (int v = 0; v < 4; v++) acc[i][j][v] = 0.f;

    // K = 80 real channels (80..95 exact zeros, skipped)
#pragma unroll
    for (int kk = 0; kk < 5; kk++) {
        uint32_t af[2][4];
#pragma unroll
        for (int im = 0; im < 2; im++)
            ldsm4(af[im][0], af[im][1], af[im][2], af[im][3],
                  aB + (im * 16 * RP + kk * 16) * 2);
        uint32_t bfr[8][2];
#pragma unroll
        for (int h = 0; h < 4; h++)
            ldsm4(bfr[2 * h][0], bfr[2 * h][1], bfr[2 * h + 1][0],
                  bfr[2 * h + 1][1], bB + (h * 16 * RP + kk * 16) * 2);
#pragma unroll
        for (int im = 0; im < 2; im++)
#pragma unroll
            for (int in = 0; in < 8; in++)
                mma16816(acc[im][in], af[im], bfr[in]);
    }

#pragma unroll
    for (int im = 0; im < 2; im++)
#pragma unroll
        for (int in = 0; in < 8; in++) {
            int s = wn * 64 + in * 8 + lc;
            float2 kv = *(float2*)&k2s[s];
            acc[im][in][0] = TEMP * (2.f * acc[im][in][0] - kv.x);
            acc[im][in][1] = TEMP * (2.f * acc[im][in][1] - kv.y);
            acc[im][in][2] = TEMP * (2.f * acc[im][in][2] - kv.x);
            acc[im][in][3] = TEMP * (2.f * acc[im][in][3] - kv.y);
        }

#pragma unroll
    for (int im = 0; im < 2; im++)
#pragma unroll
        for (int h = 0; h < 2; h++) {
            float m = -INFINITY, se = 0.f;
#pragma unroll
            for (int in = 0; in < 8; in++) {
                float v0 = acc[im][in][2 * h], v1 = acc[im][in][2 * h + 1];
                float M = fmaxf(m, fmaxf(v0, v1));
                se = se * __expf(m - M) + __expf(v0 - M) + __expf(v1 - M);
                m = M;
            }
#pragma unroll
            for (int o = 1; o <= 2; o <<= 1) {
                float m2 = __shfl_xor_sync(~0u, m, o);
                float s2 = __shfl_xor_sync(~0u, se, o);
                float M = fmaxf(m, m2);
                se = se * __expf(m - M) + s2 * __expf(m2 - M);
                m = M;
            }
            if (qq == 0) {
                int row = wm * 32 + im * 16 + h * 8 + lr;
                redM[wn * 64 + row] = m;
                redS[wn * 64 + row] = se;
            }
        }
    __syncthreads();
    if (tid < 64) {
        float M = redM[tid], SE = redS[tid];
#pragma unroll
        for (int i = 1; i < 4; i++) {
            float mi = redM[i * 64 + tid], si = redS[i * 64 + tid];
            float Mn = fmaxf(M, mi);
            SE = SE * __expf(M - Mn) + si * __expf(mi - Mn);
            M = Mn;
        }
        lseS[tid] = M + __logf(SE);
    }
    __syncthreads();

#pragma unroll
    for (int im = 0; im < 2; im++)
#pragma unroll
        for (int h = 0; h < 2; h++) {
            int row = wm * 32 + im * 16 + h * 8 + lr;
            int t = t0 + row;
            if (t < TT_TOT) {
                float lse = lseS[row];
                size_t base = ((size_t)b * TT_TOT + t) * SS;
#pragma unroll
                for (int in = 0; in < 8; in++) {
                    int s = wn * 64 + in * 8 + lc;
                    size_t o = base + s;
                    float2 pr = *(const float2*)&prior[o];
                    int2 mk = *(const int2*)&mask[o];
                    float v0 = acc[im][in][2 * h] - lse + __logf(pr.x + 1e-8f);
                    float v1 = acc[im][in][2 * h + 1] - lse + __logf(pr.y + 1e-8f);
                    float2 res;
                    res.x = mk.x ? v0 : -INFINITY;
                    res.y = mk.y ? v1 : -INFINITY;
                    *(float2*)&out[o] = res;
                }
            }
        }
}

// ---------------- launch ----------------------------------------------------
extern "C" void kernel_launch(void* const* d_in, const int* in_sizes, int n_in,
                              void* d_out, int out_size) {
    const int* phonemes = (const int*)d_in[0];
    const float* mels = (const float*)d_in[1];
    const int* mask = (const int*)d_in[2];
    const float* prior = (const float*)d_in[3];
    const float* emb = (const float*)d_in[4];
    const float* kw[5] = {(const float*)d_in[5], (const float*)d_in[7],
                          (const float*)d_in[9], (const float*)d_in[11],
                          (const float*)d_in[13]};
    const float* kb[5] = {(const float*)d_in[6], (const float*)d_in[8],
                          (const float*)d_in[10], (const float*)d_in[12],
                          (const float*)d_in[14]};
    const float* qw[3] = {(const float*)d_in[15], (const float*)d_in[17],
                          (const float*)d_in[19]};
    const float* qb[3] = {(const float*)d_in[16], (const float*)d_in[18],
                          (const float*)d_in[20]};
    float* out = (float*)d_out;

    bf16 *pA0, *pA1, *pCT, *pKT, *pMT, *pQ0, *pQ1, *pQ2, *pWT, *pEB;
    bf16* pw[7];
    float* pb0;
    cudaGetSymbolAddress((void**)&pA0, g_actT0);
    cudaGetSymbolAddress((void**)&pA1, g_actT1);
    cudaGetSymbolAddress((void**)&pCT, g_cT);
    cudaGetSymbolAddress((void**)&pKT, g_kT);
    cudaGetSymbolAddress((void**)&pMT, g_melsT);
    cudaGetSymbolAddress((void**)&pQ0, g_q0T);
    cudaGetSymbolAddress((void**)&pQ1, g_q1T);
    cudaGetSymbolAddress((void**)&pQ2, g_q2T);
    cudaGetSymbolAddress((void**)&pWT, g_wT);
    cudaGetSymbolAddress((void**)&pEB, g_embB);
    cudaGetSymbolAddress((void**)&pw[0], g_w1);
    cudaGetSymbolAddress((void**)&pw[1], g_w2);
    cudaGetSymbolAddress((void**)&pw[2], g_w3);
    cudaGetSymbolAddress((void**)&pw[3], g_w4);
    cudaGetSymbolAddress((void**)&pw[4], g_wq0);
    cudaGetSymbolAddress((void**)&pw[5], g_wq1);
    cudaGetSymbolAddress((void**)&pw[6], g_wq2);
    cudaGetSymbolAddress((void**)&pb0, g_bias0);

    // dynamic smem opt-in (3-stage ring)
    const int SM64 = 3 * 2 * 128 * 72 * 2;   // 110592
    const int SM32 = 3 * 2 * 128 * 40 * 2;   // 61440
    const int SMATT = (64 + 256) * 104 * 2 + (256 * 3 + 64) * 4;  // 69888
    cudaFuncSetAttribute(gemm_conv<5, 512, 64, true>,
                         cudaFuncAttributeMaxDynamicSharedMemorySize, SM64);
    cudaFuncSetAttribute(gemm_conv<3, 512, 64, true>,
                         cudaFuncAttributeMaxDynamicSharedMemorySize, SM64);
    cudaFuncSetAttribute(gemm_conv<1, 512, 64, false>,
                         cudaFuncAttributeMaxDynamicSharedMemorySize, SM64);
    cudaFuncSetAttribute(gemm_conv<1, 1024, 64, false>,
                         cudaFuncAttributeMaxDynamicSharedMemorySize, SM64);
    cudaFuncSetAttribute(gemm_conv<3, 96, 32, true>,
                         cudaFuncAttributeMaxDynamicSharedMemorySize, SM32);
    cudaFuncSetAttribute(gemm_conv<1, 192, 64, true>,
                         cudaFuncAttributeMaxDynamicSharedMemorySize, SM64);
    cudaFuncSetAttribute(gemm_conv<1, 128, 64, false>,
                         cudaFuncAttributeMaxDynamicSharedMemorySize, SM64);
    cudaFuncSetAttribute(attn_mma,
                         cudaFuncAttributeMaxDynamicSharedMemorySize, SMATT);

    // fork-join side stream
    cudaStream_t sQ;
    cudaStreamCreateWithFlags(&sQ, cudaStreamNonBlocking);
    cudaEvent_t evFork, evPrep, evQ;
    cudaEventCreateWithFlags(&evFork, cudaEventDisableTiming);
    cudaEventCreateWithFlags(&evPrep, cudaEventDisableTiming);
    cudaEventCreateWithFlags(&evQ, cudaEventDisableTiming);

    cudaEventRecord(evFork, 0);
    cudaStreamWaitEvent(sQ, evFork, 0);

    // side: mels transpose
    melsT_kernel<<<dim3(47, 3, BB), 256, 0, sQ>>>(mels, pMT);

    // all repacks in one launch (main). slot0 = layer0 per-tap (mode1),
    // slot1 = emb->bf16, slots 2..8 = w1,w2,w3,w4,wq0,wq1,wq2
    PrepArgs pa;
    const float* srcs[9] = {kw[0], emb,  kw[1], kw[2], kw[3],
                            kw[4], qw[0], qw[1], qw[2]};
    bf16* dsts[9] = {pWT, pEB, pw[0], pw[1], pw[2], pw[3], pw[4], pw[5], pw[6]};
    const int CoutA[9] = {0, 100, 512, 512, 1024, 80, 160, 80, 80};
    const int CinA[9] = {512, 512, 512, 512, 512, 1024, 80, 160, 80};
    const int KTA[9] = {1, 1, 5, 5, 3, 1, 3, 1, 1};
    const int CINPA[9] = {512, 512, 512, 512, 512, 1024, 96, 192, 128};
    const int RPAD[9] = {2560, 128, 512, 512, 1024, 128, 256, 128, 128};
    const int MODE[9] = {1, 0, 0, 0, 0, 0, 0, 0, 0};
    for (int i = 0; i < 9; i++) {
        pa.src[i] = srcs[i];
        pa.dst[i] = dsts[i];
        pa.Cout[i] = CoutA[i];
        pa.Cin[i] = CinA[i];
        pa.KT[i] = KTA[i];
        pa.CINP[i] = CINPA[i];
        pa.total[i] = RPAD[i] * KTA[i] * CINPA[i];
        pa.mode[i] = MODE[i];
    }
    prep_all<<<dim3(768, 9), 256>>>(pa);
    cudaEventRecord(evPrep, 0);

    // side: query encoder (fills idle SM slots of key chain)
    cudaStreamWaitEvent(sQ, evPrep, 0);
    gemm_conv<3, 96, 32, true><<<dim3(12, 2, BB), 256, SM32, sQ>>>(
        pw[4], pMT, qb[0], pQ0, 160, 192, TT_TOT);
    gemm_conv<1, 192, 64, true><<<dim3(12, 1, BB), 256, SM64, sQ>>>(
        pw[5], pQ0, qb[1], pQ1, 80, 128, TT_TOT);
    gemm_conv<1, 128, 64, false><<<dim3(12, 1, BB), 256, SM64, sQ>>>(
        pw[6], pQ1, qb[2], pQ2, 80, 96, TT_TOT);
    cudaEventRecord(evQ, sQ);

    // main: T table = wT @ embB  -> T_out[v][t*512+co] in pA0 (128 x 2560)
    gemm_conv<1, 512, 64, false><<<dim3(1, 20, 1), 256, SM64>>>(
        pWT, pEB, pb0, pA0, 2560, 2560, 128);

    // main: layer0 via gather-sum  -> pA1 [b][s][512]
    layer0_kernel<<<dim3(4, BB), 256>>>(pA0, phonemes, kb[0], pA1);

    // main: rest of key encoder
    gemm_conv<5, 512, 64, true><<<dim3(2, 4, BB), 256, SM64>>>(
        pw[0], pA1, kb[1], pA0, 512, 512, SS);
    gemm_conv<5, 512, 64, true><<<dim3(2, 4, BB), 256, SM64>>>(
        pw[1], pA0, kb[2], pA1, 512, 512, SS);
    gemm_conv<3, 512, 64, true><<<dim3(2, 8, BB), 256, SM64>>>(
        pw[2], pA1, kb[3], pCT, 1024, 1024, SS);
    gemm_conv<1, 1024, 64, false><<<dim3(2, 1, BB), 256, SM64>>>(
        pw[3], pCT, kb[4], pKT, 80, 96, SS);

    // join: attention needs the query path
    cudaStreamWaitEvent(0, evQ, 0);

    // HMMA attention + fused k2 + log_softmax + prior + mask
    attn_mma<<<dim3((TT_TOT + 63) / 64, BB), 256, SMATT>>>(pQ2, pKT, prior,
                                                           mask, out);
}